// round 11
// baseline (speedup 1.0000x reference)
#include <cuda_runtime.h>
#include <cuda_fp16.h>

#define NN 50000
#define EE 800000
#define GG 128
#define BN_EPS 1e-5f

// ---------------- scratch ----------------
__device__ float  g_deg[NN];
__device__ int    g_cnt[NN];
__device__ int    g_pos[NN];
__device__ int    g_start[NN];
__device__ int    g_csr[EE];
__device__ float  g_xe[NN * 128];
__device__ float  g_x[NN * 64];
__device__ __half g_h[NN * 64];      // fp16 hs = dinv[row]*(A@W)
__device__ float  g_o1[NN * 64];
__device__ float  g_o2[NN * 64];
__device__ float  g_bn1[128];
__device__ float  g_bn2[128];
__device__ int    g_sh;

template<int ID> __device__ __forceinline__ float* gbuf() {
    if (ID == 0) return g_xe;
    if (ID == 1) return g_x;
    if (ID == 4) return g_o1;
    if (ID == 5) return g_o2;
    return nullptr;
}
template<int ID> __device__ __forceinline__ float* gbn() {
    return (ID == 0) ? g_bn1 : g_bn2;
}

__device__ __forceinline__ int eidx(const unsigned* __restrict__ w, long long elem, int sh) {
    int v = (int)w[elem << sh];
    v = v < 0 ? 0 : v;
    return v >= NN ? NN - 1 : v;
}

__device__ __forceinline__ unsigned f2tf(float f) {
    unsigned u; asm("cvt.rna.tf32.f32 %0, %1;" : "=r"(u) : "f"(f)); return u;
}

__device__ __forceinline__ void mma_tf32(float* c, unsigned a0, unsigned a1,
                                         unsigned a2, unsigned a3,
                                         unsigned b0, unsigned b1) {
    asm volatile(
        "mma.sync.aligned.m16n8k8.row.col.f32.tf32.tf32.f32 "
        "{%0,%1,%2,%3}, {%4,%5,%6,%7}, {%8,%9}, {%0,%1,%2,%3};\n"
        : "+f"(c[0]), "+f"(c[1]), "+f"(c[2]), "+f"(c[3])
        : "r"(a0), "r"(a1), "r"(a2), "r"(a3), "r"(b0), "r"(b1));
}

// ---------------- setup / graph build ----------------
__global__ void k_setup(const unsigned* __restrict__ eiw) {
    int i = blockIdx.x * 256 + threadIdx.x;
    if (i < NN) { g_cnt[i] = 0; g_pos[i] = 0; }
    if (i < 128) { g_bn1[i] = 0.f; g_bn2[i] = 0.f; }
    if (i == 0) {
        unsigned acc = 0;
        for (int k = 0; k < 128; k++) acc |= eiw[2 * k + 1];
        g_sh = (acc == 0) ? 1 : 0;
    }
}

__global__ void k_degree(const unsigned* __restrict__ eiw) {
    int i = blockIdx.x * 256 + threadIdx.x;
    if (i >= EE) return;
    atomicAdd(&g_cnt[eidx(eiw, (long long)EE + i, g_sh)], 1);
}

__global__ void __launch_bounds__(1024) k_scanrsqrt() {
    __shared__ int ssum[1024];
    const int t = threadIdx.x;
    const int L = (NN + 1023) / 1024;
    int lo = t * L, hi = min(lo + L, NN);
    int s = 0;
    for (int i = lo; i < hi; i++) s += g_cnt[i];
    ssum[t] = s;
    __syncthreads();
    for (int off = 1; off < 1024; off <<= 1) {
        int v = (t >= off) ? ssum[t - off] : 0;
        __syncthreads();
        ssum[t] += v;
        __syncthreads();
    }
    int run = (t == 0) ? 0 : ssum[t - 1];
    for (int i = lo; i < hi; i++) {
        int c = g_cnt[i];
        g_start[i] = run;
        g_deg[i] = rsqrtf(1.0f + (float)c);
        run += c;
    }
}

__global__ void k_fill(const unsigned* __restrict__ eiw) {
    int e = blockIdx.x * 256 + threadIdx.x;
    if (e >= EE) return;
    int sh = g_sh;
    int r = eidx(eiw, e, sh);
    int c = eidx(eiw, (long long)EE + e, sh);
    int p = g_start[c] + atomicAdd(&g_pos[c], 1);
    g_csr[p] = r;
}

// ---------------- split-tf32 tensor GEMM: C[N,64] = act(A[N,K] @ W[K,64] + b) ----
// 3-term: ah*bh + al*bh + ah*bl  (~fp32 accuracy)
// MODE 0: C(float) = relu(acc+b) at stride LDC, offset DSTOFF into buf DSTB
// MODE 1: g_h(half) = dinv*acc; outb = b + dinv*hs
// MODE 3: A = relu(bn1(o1)) on load; g_h(half) = dinv*acc;
//         outb = b + dinv*hs + relu(bn1(o1))
template<int K, int MODE, int SRCB, int DSTB, int DSTOFF, int LDC, int OUTB>
__global__ void __launch_bounds__(256) k_gemm_tf32(
        const float* __restrict__ Aext, const float* __restrict__ W,
        const float* __restrict__ bias,
        const float* __restrict__ gamma, const float* __restrict__ beta)
{
    constexpr int NKT = K / 16;

    __shared__ unsigned Ah[128][20];
    __shared__ unsigned Al[128][20];
    __shared__ unsigned Wh[16][68];
    __shared__ unsigned Wl[16][68];
    __shared__ float sbn[128];

    const float* A = (SRCB < 0) ? Aext : gbuf<(SRCB >= 0) ? SRCB : 0>();
    float* C = gbuf<DSTB>() + DSTOFF;
    float* outb = gbuf<OUTB>();

    const int n0 = blockIdx.x * 128;
    const int tid = threadIdx.x;
    const int warp = tid >> 5, lane = tid & 31;
    const int l4 = lane >> 2, lm4 = lane & 3;
    const int rw = warp * 16;

    if (MODE == 3) {
        if (tid < 64) {
            float s = g_bn1[tid], q = g_bn1[64 + tid];
            float mean = s * (1.0f / NN);
            float var = fmaxf(q * (1.0f / NN) - mean * mean, 0.f);
            float scale = gamma[tid] * rsqrtf(var + BN_EPS);
            sbn[tid] = scale;
            sbn[64 + tid] = beta[tid] - mean * scale;
        }
        __syncthreads();
    }

    float acc[8][4];
#pragma unroll
    for (int j = 0; j < 8; j++)
#pragma unroll
        for (int i = 0; i < 4; i++) acc[j][i] = 0.f;

    const float4* A4 = reinterpret_cast<const float4*>(A);
    const float4* W4 = reinterpret_cast<const float4*>(W);

#pragma unroll
    for (int kt = 0; kt < NKT; kt++) {
        // stage A split into (hi, lo) tf32 bits
#pragma unroll
        for (int it = 0; it < 2; it++) {
            int idx = tid + it * 256;
            int row = idx >> 2;
            int c4 = idx & 3;
            int gn = n0 + row;
            float4 a = make_float4(0.f, 0.f, 0.f, 0.f);
            if (gn < NN) {
                a = A4[gn * (K / 4) + kt * 4 + c4];
                if (MODE == 3) {
                    int ch = kt * 16 + c4 * 4;
                    float4 sc = *reinterpret_cast<const float4*>(&sbn[ch]);
                    float4 sv = *reinterpret_cast<const float4*>(&sbn[64 + ch]);
                    a.x = fmaxf(a.x * sc.x + sv.x, 0.f);
                    a.y = fmaxf(a.y * sc.y + sv.y, 0.f);
                    a.z = fmaxf(a.z * sc.z + sv.z, 0.f);
                    a.w = fmaxf(a.w * sc.w + sv.w, 0.f);
                }
            }
            uint4 th, tl;
            th.x = f2tf(a.x); tl.x = f2tf(a.x - __uint_as_float(th.x));
            th.y = f2tf(a.y); tl.y = f2tf(a.y - __uint_as_float(th.y));
            th.z = f2tf(a.z); tl.z = f2tf(a.z - __uint_as_float(th.z));
            th.w = f2tf(a.w); tl.w = f2tf(a.w - __uint_as_float(th.w));
            *reinterpret_cast<uint4*>(&Ah[row][c4 * 4]) = th;
            *reinterpret_cast<uint4*>(&Al[row][c4 * 4]) = tl;
        }
        // stage W split
        {
            int k = tid >> 4, c4 = tid & 15;
            float4 w = W4[(kt * 16 + k) * 16 + c4];
            uint4 th, tl;
            th.x = f2tf(w.x); tl.x = f2tf(w.x - __uint_as_float(th.x));
            th.y = f2tf(w.y); tl.y = f2tf(w.y - __uint_as_float(th.y));
            th.z = f2tf(w.z); tl.z = f2tf(w.z - __uint_as_float(th.z));
            th.w = f2tf(w.w); tl.w = f2tf(w.w - __uint_as_float(th.w));
            *reinterpret_cast<uint4*>(&Wh[k][c4 * 4]) = th;
            *reinterpret_cast<uint4*>(&Wl[k][c4 * 4]) = tl;
        }
        __syncthreads();

#pragma unroll
        for (int ks = 0; ks < 2; ks++) {
            int kb = ks * 8;
            unsigned ah0 = Ah[rw + l4][kb + lm4];
            unsigned ah1 = Ah[rw + l4 + 8][kb + lm4];
            unsigned ah2 = Ah[rw + l4][kb + lm4 + 4];
            unsigned ah3 = Ah[rw + l4 + 8][kb + lm4 + 4];
            unsigned al0 = Al[rw + l4][kb + lm4];
            unsigned al1 = Al[rw + l4 + 8][kb + lm4];
            unsigned al2 = Al[rw + l4][kb + lm4 + 4];
            unsigned al3 = Al[rw + l4 + 8][kb + lm4 + 4];
#pragma unroll
            for (int j = 0; j < 8; j++) {
                unsigned bh0 = Wh[kb + lm4][j * 8 + l4];
                unsigned bh1 = Wh[kb + 4 + lm4][j * 8 + l4];
                unsigned bl0 = Wl[kb + lm4][j * 8 + l4];
                unsigned bl1 = Wl[kb + 4 + lm4][j * 8 + l4];
                mma_tf32(acc[j], ah0, ah1, ah2, ah3, bh0, bh1);
                mma_tf32(acc[j], al0, al1, al2, al3, bh0, bh1);
                mma_tf32(acc[j], ah0, ah1, ah2, ah3, bl0, bl1);
            }
        }
        __syncthreads();
    }

    // epilogue: thread owns rows r0=rw+l4, r1=r0+8; cols 8j + 2*lm4 (+1)
    int r0 = n0 + rw + l4;
    int r1 = r0 + 8;
    if (MODE == 0) {
#pragma unroll
        for (int j = 0; j < 8; j++) {
            int cj = j * 8 + lm4 * 2;
            float b0v = bias[cj], b1v = bias[cj + 1];
            if (r0 < NN) {
                float2 v = make_float2(fmaxf(acc[j][0] + b0v, 0.f),
                                       fmaxf(acc[j][1] + b1v, 0.f));
                *reinterpret_cast<float2*>(&C[r0 * LDC + cj]) = v;
            }
            if (r1 < NN) {
                float2 v = make_float2(fmaxf(acc[j][2] + b0v, 0.f),
                                       fmaxf(acc[j][3] + b1v, 0.f));
                *reinterpret_cast<float2*>(&C[r1 * LDC + cj]) = v;
            }
        }
    } else {
        float di0 = (r0 < NN) ? g_deg[r0] : 0.f;
        float di1 = (r1 < NN) ? g_deg[r1] : 0.f;
#pragma unroll
        for (int j = 0; j < 8; j++) {
            int cj = j * 8 + lm4 * 2;
            float b0v = bias[cj], b1v = bias[cj + 1];
            if (r0 < NN) {
                float hx = di0 * acc[j][0], hy = di0 * acc[j][1];
                *reinterpret_cast<__half2*>(&g_h[r0 * 64 + cj]) = __floats2half2_rn(hx, hy);
                float ox = b0v + di0 * hx, oy = b1v + di0 * hy;
                if (MODE == 3) {
                    float2 ov = *reinterpret_cast<const float2*>(&g_o1[r0 * 64 + cj]);
                    ox += fmaxf(ov.x * sbn[cj] + sbn[64 + cj], 0.f);
                    oy += fmaxf(ov.y * sbn[cj + 1] + sbn[64 + cj + 1], 0.f);
                }
                *reinterpret_cast<float2*>(&outb[r0 * 64 + cj]) = make_float2(ox, oy);
            }
            if (r1 < NN) {
                float hx = di1 * acc[j][2], hy = di1 * acc[j][3];
                *reinterpret_cast<__half2*>(&g_h[r1 * 64 + cj]) = __floats2half2_rn(hx, hy);
                float ox = b0v + di1 * hx, oy = b1v + di1 * hy;
                if (MODE == 3) {
                    float2 ov = *reinterpret_cast<const float2*>(&g_o1[r1 * 64 + cj]);
                    ox += fmaxf(ov.x * sbn[cj] + sbn[64 + cj], 0.f);
                    oy += fmaxf(ov.y * sbn[cj + 1] + sbn[64 + cj + 1], 0.f);
                }
                *reinterpret_cast<float2*>(&outb[r1 * 64 + cj]) = make_float2(ox, oy);
            }
        }
    }
}

// ---------------- gather (fp16, 8 lanes/node) + fused BN statistics ----------------
template<int OUTB, int BNB>
__global__ void __launch_bounds__(256) k_gatherbn()
{
    __shared__ float4 s0[256];
    __shared__ float4 s1[256];
    __shared__ float4 q0[256];
    __shared__ float4 q1[256];
    int tid = threadIdx.x;
    int idx = blockIdx.x * 256 + tid;
    int node = idx >> 3;          // 8 lanes per node
    int sub = idx & 7;            // lane covers channels sub*8 .. sub*8+7
    float4 o0 = make_float4(0.f, 0.f, 0.f, 0.f);
    float4 o1 = make_float4(0.f, 0.f, 0.f, 0.f);
    if (node < NN) {
        int j = g_start[node];
        int end = j + g_cnt[node];
        const uint4* h4 = reinterpret_cast<const uint4*>(g_h);
        float a[8];
#pragma unroll
        for (int k = 0; k < 8; k++) a[k] = 0.f;
        for (; j + 4 <= end; j += 4) {
            int r0 = g_csr[j], r1 = g_csr[j + 1], r2 = g_csr[j + 2], r3 = g_csr[j + 3];
            uint4 v0 = h4[r0 * 8 + sub];
            uint4 v1 = h4[r1 * 8 + sub];
            uint4 v2 = h4[r2 * 8 + sub];
            uint4 v3 = h4[r3 * 8 + sub];
#pragma unroll
            for (int p = 0; p < 4; p++) {
                float2 f0 = __half22float2(reinterpret_cast<const __half2*>(&v0)[p]);
                float2 f1 = __half22float2(reinterpret_cast<const __half2*>(&v1)[p]);
                float2 f2 = __half22float2(reinterpret_cast<const __half2*>(&v2)[p]);
                float2 f3 = __half22float2(reinterpret_cast<const __half2*>(&v3)[p]);
                a[p * 2]     += (f0.x + f1.x) + (f2.x + f3.x);
                a[p * 2 + 1] += (f0.y + f1.y) + (f2.y + f3.y);
            }
        }
        for (; j < end; j++) {
            uint4 v = h4[g_csr[j] * 8 + sub];
#pragma unroll
            for (int p = 0; p < 4; p++) {
                float2 f = __half22float2(reinterpret_cast<const __half2*>(&v)[p]);
                a[p * 2] += f.x;
                a[p * 2 + 1] += f.y;
            }
        }
        float dc = g_deg[node];
        float* op = gbuf<OUTB>() + node * 64 + sub * 8;
        o0 = *reinterpret_cast<float4*>(op);
        o1 = *reinterpret_cast<float4*>(op + 4);
        o0.x += dc * a[0]; o0.y += dc * a[1]; o0.z += dc * a[2]; o0.w += dc * a[3];
        o1.x += dc * a[4]; o1.y += dc * a[5]; o1.z += dc * a[6]; o1.w += dc * a[7];
        *reinterpret_cast<float4*>(op) = o0;
        *reinterpret_cast<float4*>(op + 4) = o1;
    }
    s0[tid] = o0; s1[tid] = o1;
    q0[tid] = make_float4(o0.x * o0.x, o0.y * o0.y, o0.z * o0.z, o0.w * o0.w);
    q1[tid] = make_float4(o1.x * o1.x, o1.y * o1.y, o1.z * o1.z, o1.w * o1.w);
    __syncthreads();
#pragma unroll
    for (int off = 128; off >= 8; off >>= 1) {
        if (tid < off) {
            float4 a4 = s0[tid], b4 = s0[tid + off];
            a4.x += b4.x; a4.y += b4.y; a4.z += b4.z; a4.w += b4.w; s0[tid] = a4;
            a4 = s1[tid]; b4 = s1[tid + off];
            a4.x += b4.x; a4.y += b4.y; a4.z += b4.z; a4.w += b4.w; s1[tid] = a4;
            a4 = q0[tid]; b4 = q0[tid + off];
            a4.x += b4.x; a4.y += b4.y; a4.z += b4.z; a4.w += b4.w; q0[tid] = a4;
            a4 = q1[tid]; b4 = q1[tid + off];
            a4.x += b4.x; a4.y += b4.y; a4.z += b4.z; a4.w += b4.w; q1[tid] = a4;
        }
        __syncthreads();
    }
    if (tid < 8) {
        float* sums = gbn<BNB>();
        int c0 = tid * 8;
        float4 a4 = s0[tid];
        atomicAdd(&sums[c0 + 0], a4.x); atomicAdd(&sums[c0 + 1], a4.y);
        atomicAdd(&sums[c0 + 2], a4.z); atomicAdd(&sums[c0 + 3], a4.w);
        a4 = s1[tid];
        atomicAdd(&sums[c0 + 4], a4.x); atomicAdd(&sums[c0 + 5], a4.y);
        atomicAdd(&sums[c0 + 6], a4.z); atomicAdd(&sums[c0 + 7], a4.w);
        a4 = q0[tid];
        atomicAdd(&sums[64 + c0 + 0], a4.x); atomicAdd(&sums[64 + c0 + 1], a4.y);
        atomicAdd(&sums[64 + c0 + 2], a4.z); atomicAdd(&sums[64 + c0 + 3], a4.w);
        a4 = q1[tid];
        atomicAdd(&sums[64 + c0 + 4], a4.x); atomicAdd(&sums[64 + c0 + 5], a4.y);
        atomicAdd(&sums[64 + c0 + 6], a4.z); atomicAdd(&sums[64 + c0 + 7], a4.w);
    }
}

// ---------------- pool + heads ----------------
__device__ __forceinline__ int lbound(const unsigned* __restrict__ bw, long long v, int sh) {
    int lo = 0, hi = NN;
    while (lo < hi) {
        int mid = (lo + hi) >> 1;
        long long bv = (long long)bw[(long long)mid << sh];
        if (bv < v) lo = mid + 1; else hi = mid;
    }
    return lo;
}

__global__ void __launch_bounds__(256) k_poolheads(const unsigned* __restrict__ bw,
        const float* __restrict__ g2, const float* __restrict__ be2,
        const float* __restrict__ Wa1, const float* __restrict__ ba1,
        const float* __restrict__ Wa2, const float* __restrict__ ba2,
        const float* __restrict__ Wo1, const float* __restrict__ bo1,
        const float* __restrict__ Wo2, const float* __restrict__ bo2,
        float* __restrict__ outp)
{
    __shared__ float sbn[128];
    __shared__ float ssum[16][64];
    __shared__ float smax[16][64];
    __shared__ float sxc[128];
    const int tid = threadIdx.x;
    const int g = blockIdx.x;

    if (tid < 64) {
        float s = g_bn2[tid], q = g_bn2[64 + tid];
        float mean = s * (1.0f / NN);
        float var = fmaxf(q * (1.0f / NN) - mean * mean, 0.f);
        float scale = g2[tid] * rsqrtf(var + BN_EPS);
        sbn[tid] = scale;
        sbn[64 + tid] = be2[tid] - mean * scale;
    }
    __syncthreads();

    const float4* X = reinterpret_cast<const float4*>(g_o2);
    int sh0 = g_sh;
    int start = lbound(bw, (long long)g, sh0);
    int end   = lbound(bw, (long long)g + 1, sh0);
    int cc = tid & 15;
    int chan = cc * 4;
    int rg = tid >> 4;
    float4 sc = *reinterpret_cast<const float4*>(&sbn[chan]);
    float4 sv = *reinterpret_cast<const float4*>(&sbn[64 + chan]);
    float4 s = make_float4(0.f, 0.f, 0.f, 0.f);
    float4 m = make_float4(0.f, 0.f, 0.f, 0.f);
    for (int n = start + rg; n < end; n += 16) {
        float4 v = X[n * 16 + cc];
        v.x = fmaxf(v.x * sc.x + sv.x, 0.f);
        v.y = fmaxf(v.y * sc.y + sv.y, 0.f);
        v.z = fmaxf(v.z * sc.z + sv.z, 0.f);
        v.w = fmaxf(v.w * sc.w + sv.w, 0.f);
        s.x += v.x; s.y += v.y; s.z += v.z; s.w += v.w;
        m.x = fmaxf(m.x, v.x); m.y = fmaxf(m.y, v.y);
        m.z = fmaxf(m.z, v.z); m.w = fmaxf(m.w, v.w);
    }
    *reinterpret_cast<float4*>(&ssum[rg][chan]) = s;
    *reinterpret_cast<float4*>(&smax[rg][chan]) = m;
    __syncthreads();
    for (int off = 8; off >= 1; off >>= 1) {
        if (rg < off) {
            float4 a  = *reinterpret_cast<float4*>(&ssum[rg][chan]);
            float4 b  = *reinterpret_cast<float4*>(&ssum[rg + off][chan]);
            a.x += b.x; a.y += b.y; a.z += b.z; a.w += b.w;
            *reinterpret_cast<float4*>(&ssum[rg][chan]) = a;
            float4 am = *reinterpret_cast<float4*>(&smax[rg][chan]);
            float4 bm = *reinterpret_cast<float4*>(&smax[rg + off][chan]);
            am.x = fmaxf(am.x, bm.x); am.y = fmaxf(am.y, bm.y);
            am.z = fmaxf(am.z, bm.z); am.w = fmaxf(am.w, bm.w);
            *reinterpret_cast<float4*>(&smax[rg][chan]) = am;
        }
        __syncthreads();
    }
    if (rg == 0) {
        float inv = 1.0f / fmaxf((float)(end - start), 1.0f);
        float4 a = *reinterpret_cast<float4*>(&ssum[0][chan]);
        sxc[chan + 0] = a.x * inv; sxc[chan + 1] = a.y * inv;
        sxc[chan + 2] = a.z * inv; sxc[chan + 3] = a.w * inv;
        float4 mm = *reinterpret_cast<float4*>(&smax[0][chan]);
        sxc[64 + chan + 0] = mm.x; sxc[64 + chan + 1] = mm.y;
        sxc[64 + chan + 2] = mm.z; sxc[64 + chan + 3] = mm.w;
    }
    __syncthreads();

    int wid = tid >> 5;
    if (wid < 2) {
        int lane = tid & 31;
        int head = wid;
        const float* W1p = head ? Wo1 : Wa1;
        const float* b1p = head ? bo1 : ba1;
        const float* W2p = head ? Wo2 : Wa2;
        const float* b2p = head ? bo2 : ba2;
        float a0 = b1p[lane], a1 = b1p[lane + 32];
#pragma unroll 4
        for (int k = 0; k < 128; k++) {
            float v = sxc[k];
            a0 += v * W1p[k * 64 + lane];
            a1 += v * W1p[k * 64 + lane + 32];
        }
        a0 = fmaxf(a0, 0.f); a1 = fmaxf(a1, 0.f);
        float o = a0 * W2p[lane] + a1 * W2p[lane + 32];
#pragma unroll
        for (int off = 16; off; off >>= 1) o += __shfl_xor_sync(0xffffffffu, o, off);
        if (lane == 0) outp[head * GG + g] = o + b2p[0];
    }
}

// ---------------- launch ----------------
extern "C" void kernel_launch(void* const* d_in, const int* in_sizes, int n_in,
                              void* d_out, int out_size)
{
    const float*    metadata = (const float*)d_in[0];
    const float*    wf       = (const float*)d_in[1];
    const unsigned* eiw      = (const unsigned*)d_in[2];
    const unsigned* batchw   = (const unsigned*)d_in[3];
    const float* Wm  = (const float*)d_in[4];
    const float* bm  = (const float*)d_in[5];
    const float* Ww  = (const float*)d_in[6];
    const float* bw  = (const float*)d_in[7];
    const float* Wc  = (const float*)d_in[8];
    const float* bc  = (const float*)d_in[9];
    const float* W1  = (const float*)d_in[10];
    const float* b1  = (const float*)d_in[11];
    const float* W2  = (const float*)d_in[12];
    const float* b2  = (const float*)d_in[13];
    const float* g1  = (const float*)d_in[14];
    const float* be1 = (const float*)d_in[15];
    const float* g2  = (const float*)d_in[16];
    const float* be2 = (const float*)d_in[17];
    const float* Wla1 = (const float*)d_in[18];
    const float* bla1 = (const float*)d_in[19];
    const float* Wla2 = (const float*)d_in[20];
    const float* bla2 = (const float*)d_in[21];
    const float* Wlo1 = (const float*)d_in[22];
    const float* blo1 = (const float*)d_in[23];
    const float* Wlo2 = (const float*)d_in[24];
    const float* blo2 = (const float*)d_in[25];
    float* outp = (float*)d_out;

    const int NB = (NN + 255) / 256;
    const int EB = (EE + 255) / 256;
    const int GB = (NN + 127) / 128;          // 391
    const int AB = (NN * 8 + 255) / 256;      // 1563

    k_setup<<<NB, 256>>>(eiw);
    k_degree<<<EB, 256>>>(eiw);
    k_scanrsqrt<<<1, 1024>>>();
    k_fill<<<EB, 256>>>(eiw);

    // encoders: me -> xe[:, :64], we -> xe[:, 64:], x = relu(xe @ Wc + bc)
    k_gemm_tf32<16,  0, -1, 0, 0,  128, 0><<<GB, 256>>>(metadata, Wm, bm, nullptr, nullptr);
    k_gemm_tf32<128, 0, -1, 0, 64, 128, 0><<<GB, 256>>>(wf, Ww, bw, nullptr, nullptr);
    k_gemm_tf32<128, 0,  0, 1, 0,  64,  0><<<GB, 256>>>(nullptr, Wc, bc, nullptr, nullptr);

    // GCN layer 1
    k_gemm_tf32<64, 1, 1, 0, 0, 64, 4><<<GB, 256>>>(nullptr, W1, b1, nullptr, nullptr);
    k_gatherbn<4, 0><<<AB, 256>>>();

    // GCN layer 2 (bn1-on-load + residual)
    k_gemm_tf32<64, 3, 4, 0, 0, 64, 5><<<GB, 256>>>(nullptr, W2, b2, g1, be1);
    k_gatherbn<5, 1><<<AB, 256>>>();

    k_poolheads<<<GG, 256>>>(batchw, g2, be2,
                             Wla1, bla1, Wla2, bla2, Wlo1, blo1, Wlo2, blo2, outp);
}

// round 13
// speedup vs baseline: 1.1176x; 1.1176x over previous
#include <cuda_runtime.h>

#define NN 50000
#define EE 800000
#define GG 128
#define BN_EPS 1e-5f

// ---------------- scratch ----------------
__device__ float g_deg[NN];
__device__ int   g_cnt[NN];
__device__ int   g_pos[NN];
__device__ int   g_start[NN];
__device__ int   g_csr[EE];
__device__ float g_x[NN * 64];
__device__ float g_h[NN * 64];
__device__ float g_o1[NN * 64];
__device__ float g_o2[NN * 64];
__device__ float g_bn1[128];
__device__ float g_bn2[128];
__device__ int   g_sh;

template<int ID> __device__ __forceinline__ float* gbuf() {
    if (ID == 1) return g_x;
    if (ID == 4) return g_o1;
    if (ID == 5) return g_o2;
    return nullptr;
}
template<int ID> __device__ __forceinline__ float* gbn() {
    return (ID == 0) ? g_bn1 : g_bn2;
}

__device__ __forceinline__ int eidx(const unsigned* __restrict__ w, long long elem, int sh) {
    int v = (int)w[elem << sh];
    v = v < 0 ? 0 : v;
    return v >= NN ? NN - 1 : v;
}

__device__ __forceinline__ unsigned f2tf(float f) {
    unsigned u; asm("cvt.rna.tf32.f32 %0, %1;" : "=r"(u) : "f"(f)); return u;
}

__device__ __forceinline__ void mma_tf32(float* c, unsigned a0, unsigned a1,
                                         unsigned a2, unsigned a3,
                                         unsigned b0, unsigned b1) {
    asm volatile(
        "mma.sync.aligned.m16n8k8.row.col.f32.tf32.tf32.f32 "
        "{%0,%1,%2,%3}, {%4,%5,%6,%7}, {%8,%9}, {%0,%1,%2,%3};\n"
        : "+f"(c[0]), "+f"(c[1]), "+f"(c[2]), "+f"(c[3])
        : "r"(a0), "r"(a1), "r"(a2), "r"(a3), "r"(b0), "r"(b1));
}

// ---------------- setup / graph build ----------------
__global__ void k_setup(const unsigned* __restrict__ eiw) {
    int i = blockIdx.x * 256 + threadIdx.x;
    if (i < NN) { g_cnt[i] = 0; g_pos[i] = 0; }
    if (i < 128) { g_bn1[i] = 0.f; g_bn2[i] = 0.f; }
    if (i == 0) {
        unsigned acc = 0;
        for (int k = 0; k < 128; k++) acc |= eiw[2 * k + 1];
        g_sh = (acc == 0) ? 1 : 0;
    }
}

__global__ void k_degree(const unsigned* __restrict__ eiw) {
    int i = blockIdx.x * 256 + threadIdx.x;
    if (i >= EE) return;
    atomicAdd(&g_cnt[eidx(eiw, (long long)EE + i, g_sh)], 1);
}

__global__ void __launch_bounds__(1024) k_scanrsqrt() {
    __shared__ int ssum[1024];
    const int t = threadIdx.x;
    const int L = (NN + 1023) / 1024;
    int lo = t * L, hi = min(lo + L, NN);
    int s = 0;
    for (int i = lo; i < hi; i++) s += g_cnt[i];
    ssum[t] = s;
    __syncthreads();
    for (int off = 1; off < 1024; off <<= 1) {
        int v = (t >= off) ? ssum[t - off] : 0;
        __syncthreads();
        ssum[t] += v;
        __syncthreads();
    }
    int run = (t == 0) ? 0 : ssum[t - 1];
    for (int i = lo; i < hi; i++) {
        int c = g_cnt[i];
        g_start[i] = run;
        g_deg[i] = rsqrtf(1.0f + (float)c);
        run += c;
    }
}

__global__ void k_fill(const unsigned* __restrict__ eiw) {
    int e = blockIdx.x * 256 + threadIdx.x;
    if (e >= EE) return;
    int sh = g_sh;
    int r = eidx(eiw, e, sh);
    int c = eidx(eiw, (long long)EE + e, sh);
    int p = g_start[c] + atomicAdd(&g_pos[c], 1);
    g_csr[p] = r;
}

// ---------------- fused tf32 encoder ----------------
// x = relu([relu(m@Wm+bm) | relu(wf@Ww+bw)] @ Wc + bc)
// Stage-1 intermediate stored as tf32 bits in smem (aliased with stage-1 staging).
__global__ void __launch_bounds__(256) k_enc(
        const float* __restrict__ metadata, const float* __restrict__ wf,
        const float* __restrict__ Wm, const float* __restrict__ bm,
        const float* __restrict__ Ww, const float* __restrict__ bw,
        const float* __restrict__ Wc, const float* __restrict__ bc)
{
    // union buffer: stage-1 A staging Asm[128][20] (10.2KB) OR intermediate As2[128][68] (34.8KB)
    __shared__ unsigned SB[128 * 68];
    __shared__ unsigned Wsm[16][68];
#define ASM(r, k) SB[(r) * 20 + (k)]
#define AS2(r, c) SB[(r) * 68 + (c)]

    const int n0 = blockIdx.x * 128;
    const int tid = threadIdx.x;
    const int warp = tid >> 5, lane = tid & 31;
    const int l4 = lane >> 2, lm4 = lane & 3;
    const int rw = warp * 16;

    const float4* Wc4 = reinterpret_cast<const float4*>(Wc);

    float acc2[8][4];
#pragma unroll
    for (int j = 0; j < 8; j++)
#pragma unroll
        for (int i = 0; i < 4; i++) acc2[j][i] = 0.f;

#pragma unroll
    for (int half = 0; half < 2; half++) {
        const float* Ain = half ? wf : metadata;
        const float* W1p = half ? Ww : Wm;
        const float* B1p = half ? bw : bm;
        const int K = half ? 128 : 16;
        const float4* A4 = reinterpret_cast<const float4*>(Ain);
        const float4* W14 = reinterpret_cast<const float4*>(W1p);

        float acc[8][4];
#pragma unroll
        for (int j = 0; j < 8; j++)
#pragma unroll
            for (int i = 0; i < 4; i++) acc[j][i] = 0.f;

        // ---- stage 1: acc = Ain @ W1 (tf32 MMA) ----
        for (int kt = 0; kt < K / 16; kt++) {
#pragma unroll
            for (int it = 0; it < 2; it++) {
                int idx = tid + it * 256;
                int row = idx >> 2, c4 = idx & 3;
                int gn = n0 + row;
                float4 a = make_float4(0.f, 0.f, 0.f, 0.f);
                if (gn < NN) a = A4[gn * (K / 4) + kt * 4 + c4];
                ASM(row, c4 * 4 + 0) = f2tf(a.x);
                ASM(row, c4 * 4 + 1) = f2tf(a.y);
                ASM(row, c4 * 4 + 2) = f2tf(a.z);
                ASM(row, c4 * 4 + 3) = f2tf(a.w);
            }
            {
                int k = tid >> 4, c4 = tid & 15;
                float4 w = W14[(kt * 16 + k) * 16 + c4];
                Wsm[k][c4 * 4 + 0] = f2tf(w.x);
                Wsm[k][c4 * 4 + 1] = f2tf(w.y);
                Wsm[k][c4 * 4 + 2] = f2tf(w.z);
                Wsm[k][c4 * 4 + 3] = f2tf(w.w);
            }
            __syncthreads();
#pragma unroll
            for (int ks = 0; ks < 2; ks++) {
                int kb = ks * 8;
                unsigned a0 = ASM(rw + l4, kb + lm4);
                unsigned a1 = ASM(rw + l4 + 8, kb + lm4);
                unsigned a2 = ASM(rw + l4, kb + lm4 + 4);
                unsigned a3 = ASM(rw + l4 + 8, kb + lm4 + 4);
#pragma unroll
                for (int j = 0; j < 8; j++) {
                    unsigned b0 = Wsm[kb + lm4][j * 8 + l4];
                    unsigned b1 = Wsm[kb + 4 + lm4][j * 8 + l4];
                    mma_tf32(acc[j], a0, a1, a2, a3, b0, b1);
                }
            }
            __syncthreads();
        }

        // ---- write relu(acc + b1) as tf32 into As2 (aliases Asm; all reads done) ----
#pragma unroll
        for (int j = 0; j < 8; j++) {
            int cj = j * 8 + lm4 * 2;
            float b0v = B1p[cj], b1v = B1p[cj + 1];
            int r0 = rw + l4, r1 = r0 + 8;
            AS2(r0, cj)     = f2tf(fmaxf(acc[j][0] + b0v, 0.f));
            AS2(r0, cj + 1) = f2tf(fmaxf(acc[j][1] + b1v, 0.f));
            AS2(r1, cj)     = f2tf(fmaxf(acc[j][2] + b0v, 0.f));
            AS2(r1, cj + 1) = f2tf(fmaxf(acc[j][3] + b1v, 0.f));
        }
        __syncthreads();

        // ---- stage 2: acc2 += As2 @ Wc[half*64 .. half*64+63] ----
        for (int kt = 0; kt < 4; kt++) {
            {
                int k = tid >> 4, c4 = tid & 15;
                float4 w = Wc4[(half * 64 + kt * 16 + k) * 16 + c4];
                Wsm[k][c4 * 4 + 0] = f2tf(w.x);
                Wsm[k][c4 * 4 + 1] = f2tf(w.y);
                Wsm[k][c4 * 4 + 2] = f2tf(w.z);
                Wsm[k][c4 * 4 + 3] = f2tf(w.w);
            }
            __syncthreads();
#pragma unroll
            for (int ks = 0; ks < 2; ks++) {
                int ka = kt * 16 + ks * 8;
                int kw = ks * 8;
                unsigned a0 = AS2(rw + l4, ka + lm4);
                unsigned a1 = AS2(rw + l4 + 8, ka + lm4);
                unsigned a2 = AS2(rw + l4, ka + lm4 + 4);
                unsigned a3 = AS2(rw + l4 + 8, ka + lm4 + 4);
#pragma unroll
                for (int j = 0; j < 8; j++) {
                    unsigned b0 = Wsm[kw + lm4][j * 8 + l4];
                    unsigned b1 = Wsm[kw + 4 + lm4][j * 8 + l4];
                    mma_tf32(acc2[j], a0, a1, a2, a3, b0, b1);
                }
            }
            __syncthreads();
        }
    }

    // ---- final epilogue: g_x = relu(acc2 + bc) ----
    int r0 = n0 + rw + l4;
    int r1 = r0 + 8;
#pragma unroll
    for (int j = 0; j < 8; j++) {
        int cj = j * 8 + lm4 * 2;
        float b0v = bc[cj], b1v = bc[cj + 1];
        if (r0 < NN) {
            float2 v = make_float2(fmaxf(acc2[j][0] + b0v, 0.f),
                                   fmaxf(acc2[j][1] + b1v, 0.f));
            *reinterpret_cast<float2*>(&g_x[r0 * 64 + cj]) = v;
        }
        if (r1 < NN) {
            float2 v = make_float2(fmaxf(acc2[j][2] + b0v, 0.f),
                                   fmaxf(acc2[j][3] + b1v, 0.f));
            *reinterpret_cast<float2*>(&g_x[r1 * 64 + cj]) = v;
        }
    }
#undef ASM
#undef AS2
}

// ---------------- GCN tf32 GEMM (K=64): hs = dinv*(A@W) -> g_h; seed outb ----------------
// MODE 1: A = g_x;            outb = b + dinv*hs
// MODE 3: A = relu(bn1(o1));  outb = b + dinv*hs + relu(bn1(o1))
template<int MODE, int SRCB, int OUTB>
__global__ void __launch_bounds__(256) k_gcn_gemm(
        const float* __restrict__ W, const float* __restrict__ bias,
        const float* __restrict__ gamma, const float* __restrict__ beta)
{
    __shared__ unsigned Asm[128][20];
    __shared__ unsigned Wsm[16][68];
    __shared__ float sbn[128];

    const float* A = gbuf<SRCB>();
    float* outb = gbuf<OUTB>();

    const int n0 = blockIdx.x * 128;
    const int tid = threadIdx.x;
    const int warp = tid >> 5, lane = tid & 31;
    const int l4 = lane >> 2, lm4 = lane & 3;
    const int rw = warp * 16;

    if (MODE == 3) {
        if (tid < 64) {
            float s = g_bn1[tid], q = g_bn1[64 + tid];
            float mean = s * (1.0f / NN);
            float var = fmaxf(q * (1.0f / NN) - mean * mean, 0.f);
            float scale = gamma[tid] * rsqrtf(var + BN_EPS);
            sbn[tid] = scale;
            sbn[64 + tid] = beta[tid] - mean * scale;
        }
        __syncthreads();
    }

    float acc[8][4];
#pragma unroll
    for (int j = 0; j < 8; j++)
#pragma unroll
        for (int i = 0; i < 4; i++) acc[j][i] = 0.f;

    const float4* A4 = reinterpret_cast<const float4*>(A);
    const float4* W4 = reinterpret_cast<const float4*>(W);

#pragma unroll
    for (int kt = 0; kt < 4; kt++) {
#pragma unroll
        for (int it = 0; it < 2; it++) {
            int idx = tid + it * 256;
            int row = idx >> 2, c4 = idx & 3;
            int gn = n0 + row;
            float4 a = make_float4(0.f, 0.f, 0.f, 0.f);
            if (gn < NN) {
                a = A4[gn * 16 + kt * 4 + c4];
                if (MODE == 3) {
                    int ch = kt * 16 + c4 * 4;
                    float4 sc = *reinterpret_cast<const float4*>(&sbn[ch]);
                    float4 sv = *reinterpret_cast<const float4*>(&sbn[64 + ch]);
                    a.x = fmaxf(a.x * sc.x + sv.x, 0.f);
                    a.y = fmaxf(a.y * sc.y + sv.y, 0.f);
                    a.z = fmaxf(a.z * sc.z + sv.z, 0.f);
                    a.w = fmaxf(a.w * sc.w + sv.w, 0.f);
                }
            }
            Asm[row][c4 * 4 + 0] = f2tf(a.x);
            Asm[row][c4 * 4 + 1] = f2tf(a.y);
            Asm[row][c4 * 4 + 2] = f2tf(a.z);
            Asm[row][c4 * 4 + 3] = f2tf(a.w);
        }
        {
            int k = tid >> 4, c4 = tid & 15;
            float4 w = W4[(kt * 16 + k) * 16 + c4];
            Wsm[k][c4 * 4 + 0] = f2tf(w.x);
            Wsm[k][c4 * 4 + 1] = f2tf(w.y);
            Wsm[k][c4 * 4 + 2] = f2tf(w.z);
            Wsm[k][c4 * 4 + 3] = f2tf(w.w);
        }
        __syncthreads();
#pragma unroll
        for (int ks = 0; ks < 2; ks++) {
            int kb = ks * 8;
            unsigned a0 = Asm[rw + l4][kb + lm4];
            unsigned a1 = Asm[rw + l4 + 8][kb + lm4];
            unsigned a2 = Asm[rw + l4][kb + lm4 + 4];
            unsigned a3 = Asm[rw + l4 + 8][kb + lm4 + 4];
#pragma unroll
            for (int j = 0; j < 8; j++) {
                unsigned b0 = Wsm[kb + lm4][j * 8 + l4];
                unsigned b1 = Wsm[kb + 4 + lm4][j * 8 + l4];
                mma_tf32(acc[j], a0, a1, a2, a3, b0, b1);
            }
        }
        __syncthreads();
    }

    int r0 = n0 + rw + l4;
    int r1 = r0 + 8;
    float di0 = (r0 < NN) ? g_deg[r0] : 0.f;
    float di1 = (r1 < NN) ? g_deg[r1] : 0.f;
#pragma unroll
    for (int j = 0; j < 8; j++) {
        int cj = j * 8 + lm4 * 2;
        float b0v = bias[cj], b1v = bias[cj + 1];
        if (r0 < NN) {
            float hx = di0 * acc[j][0], hy = di0 * acc[j][1];
            *reinterpret_cast<float2*>(&g_h[r0 * 64 + cj]) = make_float2(hx, hy);
            float ox = b0v + di0 * hx, oy = b1v + di0 * hy;
            if (MODE == 3) {
                float2 ov = *reinterpret_cast<const float2*>(&g_o1[r0 * 64 + cj]);
                ox += fmaxf(ov.x * sbn[cj] + sbn[64 + cj], 0.f);
                oy += fmaxf(ov.y * sbn[cj + 1] + sbn[64 + cj + 1], 0.f);
            }
            *reinterpret_cast<float2*>(&outb[r0 * 64 + cj]) = make_float2(ox, oy);
        }
        if (r1 < NN) {
            float hx = di1 * acc[j][2], hy = di1 * acc[j][3];
            *reinterpret_cast<float2*>(&g_h[r1 * 64 + cj]) = make_float2(hx, hy);
            float ox = b0v + di1 * hx, oy = b1v + di1 * hy;
            if (MODE == 3) {
                float2 ov = *reinterpret_cast<const float2*>(&g_o1[r1 * 64 + cj]);
                ox += fmaxf(ov.x * sbn[cj] + sbn[64 + cj], 0.f);
                oy += fmaxf(ov.y * sbn[cj + 1] + sbn[64 + cj + 1], 0.f);
            }
            *reinterpret_cast<float2*>(&outb[r1 * 64 + cj]) = make_float2(ox, oy);
        }
    }
}

// ---------------- gather + fused BN statistics (fp32, 16 lanes/node) ----------------
template<int OUTB, int BNB>
__global__ void __launch_bounds__(256) k_gatherbn()
{
    __shared__ float4 ss[256];
    __shared__ float4 sq[256];
    int tid = threadIdx.x;
    int idx = blockIdx.x * 256 + tid;
    int node = idx >> 4;
    int sub = idx & 15;
    float4 o = make_float4(0.f, 0.f, 0.f, 0.f);
    if (node < NN) {
        int j = g_start[node];
        int end = j + g_cnt[node];
        const float4* hs4 = reinterpret_cast<const float4*>(g_h);
        float4 acc = make_float4(0.f, 0.f, 0.f, 0.f);
        for (; j + 4 <= end; j += 4) {
            int r0 = g_csr[j], r1 = g_csr[j + 1], r2 = g_csr[j + 2], r3 = g_csr[j + 3];
            float4 v0 = hs4[r0 * 16 + sub];
            float4 v1 = hs4[r1 * 16 + sub];
            float4 v2 = hs4[r2 * 16 + sub];
            float4 v3 = hs4[r3 * 16 + sub];
            acc.x += (v0.x + v1.x) + (v2.x + v3.x);
            acc.y += (v0.y + v1.y) + (v2.y + v3.y);
            acc.z += (v0.z + v1.z) + (v2.z + v3.z);
            acc.w += (v0.w + v1.w) + (v2.w + v3.w);
        }
        for (; j < end; j++) {
            float4 v = hs4[g_csr[j] * 16 + sub];
            acc.x += v.x; acc.y += v.y; acc.z += v.z; acc.w += v.w;
        }
        float dc = g_deg[node];
        float4* out4 = reinterpret_cast<float4*>(gbuf<OUTB>());
        o = out4[node * 16 + sub];
        o.x += dc * acc.x; o.y += dc * acc.y; o.z += dc * acc.z; o.w += dc * acc.w;
        out4[node * 16 + sub] = o;
    }
    ss[tid] = o;
    sq[tid] = make_float4(o.x * o.x, o.y * o.y, o.z * o.z, o.w * o.w);
    __syncthreads();
#pragma unroll
    for (int off = 128; off >= 16; off >>= 1) {
        if (tid < off) {
            float4 a = ss[tid], b = ss[tid + off];
            a.x += b.x; a.y += b.y; a.z += b.z; a.w += b.w;
            ss[tid] = a;
            float4 c = sq[tid], d = sq[tid + off];
            c.x += d.x; c.y += d.y; c.z += d.z; c.w += d.w;
            sq[tid] = c;
        }
        __syncthreads();
    }
    if (tid < 16) {
        float* sums = gbn<BNB>();
        float4 a = ss[tid], c = sq[tid];
        atomicAdd(&sums[tid * 4 + 0], a.x); atomicAdd(&sums[tid * 4 + 1], a.y);
        atomicAdd(&sums[tid * 4 + 2], a.z); atomicAdd(&sums[tid * 4 + 3], a.w);
        atomicAdd(&sums[64 + tid * 4 + 0], c.x); atomicAdd(&sums[64 + tid * 4 + 1], c.y);
        atomicAdd(&sums[64 + tid * 4 + 2], c.z); atomicAdd(&sums[64 + tid * 4 + 3], c.w);
    }
}

// ---------------- pool + heads ----------------
__device__ __forceinline__ int lbound(const unsigned* __restrict__ bw, long long v, int sh) {
    int lo = 0, hi = NN;
    while (lo < hi) {
        int mid = (lo + hi) >> 1;
        long long bv = (long long)bw[(long long)mid << sh];
        if (bv < v) lo = mid + 1; else hi = mid;
    }
    return lo;
}

__global__ void __launch_bounds__(256) k_poolheads(const unsigned* __restrict__ bw,
        const float* __restrict__ g2, const float* __restrict__ be2,
        const float* __restrict__ Wa1, const float* __restrict__ ba1,
        const float* __restrict__ Wa2, const float* __restrict__ ba2,
        const float* __restrict__ Wo1, const float* __restrict__ bo1,
        const float* __restrict__ Wo2, const float* __restrict__ bo2,
        float* __restrict__ outp)
{
    __shared__ float sbn[128];
    __shared__ float ssum[16][64];
    __shared__ float smax[16][64];
    __shared__ float sxc[128];
    const int tid = threadIdx.x;
    const int g = blockIdx.x;

    if (tid < 64) {
        float s = g_bn2[tid], q = g_bn2[64 + tid];
        float mean = s * (1.0f / NN);
        float var = fmaxf(q * (1.0f / NN) - mean * mean, 0.f);
        float scale = g2[tid] * rsqrtf(var + BN_EPS);
        sbn[tid] = scale;
        sbn[64 + tid] = be2[tid] - mean * scale;
    }
    __syncthreads();

    const float4* X = reinterpret_cast<const float4*>(g_o2);
    int sh0 = g_sh;
    int start = lbound(bw, (long long)g, sh0);
    int end   = lbound(bw, (long long)g + 1, sh0);
    int cc = tid & 15;
    int chan = cc * 4;
    int rg = tid >> 4;
    float4 sc = *reinterpret_cast<const float4*>(&sbn[chan]);
    float4 sv = *reinterpret_cast<const float4*>(&sbn[64 + chan]);
    float4 s = make_float4(0.f, 0.f, 0.f, 0.f);
    float4 m = make_float4(0.f, 0.f, 0.f, 0.f);
    for (int n = start + rg; n < end; n += 16) {
        float4 v = X[n * 16 + cc];
        v.x = fmaxf(v.x * sc.x + sv.x, 0.f);
        v.y = fmaxf(v.y * sc.y + sv.y, 0.f);
        v.z = fmaxf(v.z * sc.z + sv.z, 0.f);
        v.w = fmaxf(v.w * sc.w + sv.w, 0.f);
        s.x += v.x; s.y += v.y; s.z += v.z; s.w += v.w;
        m.x = fmaxf(m.x, v.x); m.y = fmaxf(m.y, v.y);
        m.z = fmaxf(m.z, v.z); m.w = fmaxf(m.w, v.w);
    }
    *reinterpret_cast<float4*>(&ssum[rg][chan]) = s;
    *reinterpret_cast<float4*>(&smax[rg][chan]) = m;
    __syncthreads();
    for (int off = 8; off >= 1; off >>= 1) {
        if (rg < off) {
            float4 a  = *reinterpret_cast<float4*>(&ssum[rg][chan]);
            float4 b  = *reinterpret_cast<float4*>(&ssum[rg + off][chan]);
            a.x += b.x; a.y += b.y; a.z += b.z; a.w += b.w;
            *reinterpret_cast<float4*>(&ssum[rg][chan]) = a;
            float4 am = *reinterpret_cast<float4*>(&smax[rg][chan]);
            float4 bm = *reinterpret_cast<float4*>(&smax[rg + off][chan]);
            am.x = fmaxf(am.x, bm.x); am.y = fmaxf(am.y, bm.y);
            am.z = fmaxf(am.z, bm.z); am.w = fmaxf(am.w, bm.w);
            *reinterpret_cast<float4*>(&smax[rg][chan]) = am;
        }
        __syncthreads();
    }
    if (rg == 0) {
        float inv = 1.0f / fmaxf((float)(end - start), 1.0f);
        float4 a = *reinterpret_cast<float4*>(&ssum[0][chan]);
        sxc[chan + 0] = a.x * inv; sxc[chan + 1] = a.y * inv;
        sxc[chan + 2] = a.z * inv; sxc[chan + 3] = a.w * inv;
        float4 mm = *reinterpret_cast<float4*>(&smax[0][chan]);
        sxc[64 + chan + 0] = mm.x; sxc[64 + chan + 1] = mm.y;
        sxc[64 + chan + 2] = mm.z; sxc[64 + chan + 3] = mm.w;
    }
    __syncthreads();

    int wid = tid >> 5;
    if (wid < 2) {
        int lane = tid & 31;
        int head = wid;
        const float* W1p = head ? Wo1 : Wa1;
        const float* b1p = head ? bo1 : ba1;
        const float* W2p = head ? Wo2 : Wa2;
        const float* b2p = head ? bo2 : ba2;
        float a0 = b1p[lane], a1 = b1p[lane + 32];
#pragma unroll 4
        for (int k = 0; k < 128; k++) {
            float v = sxc[k];
            a0 += v * W1p[k * 64 + lane];
            a1 += v * W1p[k * 64 + lane + 32];
        }
        a0 = fmaxf(a0, 0.f); a1 = fmaxf(a1, 0.f);
        float o = a0 * W2p[lane] + a1 * W2p[lane + 32];
#pragma unroll
        for (int off = 16; off; off >>= 1) o += __shfl_xor_sync(0xffffffffu, o, off);
        if (lane == 0) outp[head * GG + g] = o + b2p[0];
    }
}

// ---------------- launch ----------------
extern "C" void kernel_launch(void* const* d_in, const int* in_sizes, int n_in,
                              void* d_out, int out_size)
{
    const float*    metadata = (const float*)d_in[0];
    const float*    wf       = (const float*)d_in[1];
    const unsigned* eiw      = (const unsigned*)d_in[2];
    const unsigned* batchw   = (const unsigned*)d_in[3];
    const float* Wm  = (const float*)d_in[4];
    const float* bm  = (const float*)d_in[5];
    const float* Ww  = (const float*)d_in[6];
    const float* bw  = (const float*)d_in[7];
    const float* Wc  = (const float*)d_in[8];
    const float* bc  = (const float*)d_in[9];
    const float* W1  = (const float*)d_in[10];
    const float* b1  = (const float*)d_in[11];
    const float* W2  = (const float*)d_in[12];
    const float* b2  = (const float*)d_in[13];
    const float* g1  = (const float*)d_in[14];
    const float* be1 = (const float*)d_in[15];
    const float* g2  = (const float*)d_in[16];
    const float* be2 = (const float*)d_in[17];
    const float* Wla1 = (const float*)d_in[18];
    const float* bla1 = (const float*)d_in[19];
    const float* Wla2 = (const float*)d_in[20];
    const float* bla2 = (const float*)d_in[21];
    const float* Wlo1 = (const float*)d_in[22];
    const float* blo1 = (const float*)d_in[23];
    const float* Wlo2 = (const float*)d_in[24];
    const float* blo2 = (const float*)d_in[25];
    float* outp = (float*)d_out;

    const int NB = (NN + 255) / 256;
    const int EB = (EE + 255) / 256;
    const int GB = (NN + 127) / 128;          // 391
    const int AB = (NN * 16 + 255) / 256;     // 3125

    k_setup<<<NB, 256>>>(eiw);
    k_degree<<<EB, 256>>>(eiw);
    k_scanrsqrt<<<1, 1024>>>();
    k_fill<<<EB, 256>>>(eiw);

    k_enc<<<GB, 256>>>(metadata, wf, Wm, bm, Ww, bw, Wc, bc);

    k_gcn_gemm<1, 1, 4><<<GB, 256>>>(W1, b1, nullptr, nullptr);
    k_gatherbn<4, 0><<<AB, 256>>>();

    k_gcn_gemm<3, 4, 5><<<GB, 256>>>(W2, b2, g1, be1);
    k_gatherbn<5, 1><<<AB, 256>>>();

    k_poolheads<<<GG, 256>>>(batchw, g2, be2,
                             Wla1, bla1, Wla2, bla2, Wlo1, blo1, Wlo2, blo2, outp);
}

// round 14
// speedup vs baseline: 1.1426x; 1.0224x over previous
#include <cuda_runtime.h>

#define NN 50000
#define EE 800000
#define GG 128
#define BN_EPS 1e-5f

// ---------------- scratch ----------------
__device__ float g_deg[NN];
__device__ int   g_cnt[NN];
__device__ int   g_pos[NN];
__device__ int   g_start[NN];
__device__ int   g_csr[EE];
__device__ float g_x[NN * 64];
__device__ float g_h[NN * 64];
__device__ float g_o1[NN * 64];
__device__ float g_o2[NN * 64];
__device__ float g_bn1[128];
__device__ float g_bn2[128];
__device__ int   g_sh;

template<int ID> __device__ __forceinline__ float* gbuf() {
    if (ID == 1) return g_x;
    if (ID == 4) return g_o1;
    if (ID == 5) return g_o2;
    return nullptr;
}
template<int ID> __device__ __forceinline__ float* gbn() {
    return (ID == 0) ? g_bn1 : g_bn2;
}

__device__ __forceinline__ int eidx(const unsigned* __restrict__ w, long long elem, int sh) {
    int v = (int)w[elem << sh];
    v = v < 0 ? 0 : v;
    return v >= NN ? NN - 1 : v;
}

__device__ __forceinline__ unsigned f2tf(float f) {
    unsigned u; asm("cvt.rna.tf32.f32 %0, %1;" : "=r"(u) : "f"(f)); return u;
}

__device__ __forceinline__ void mma_tf32(float* c, unsigned a0, unsigned a1,
                                         unsigned a2, unsigned a3,
                                         unsigned b0, unsigned b1) {
    asm volatile(
        "mma.sync.aligned.m16n8k8.row.col.f32.tf32.tf32.f32 "
        "{%0,%1,%2,%3}, {%4,%5,%6,%7}, {%8,%9}, {%0,%1,%2,%3};\n"
        : "+f"(c[0]), "+f"(c[1]), "+f"(c[2]), "+f"(c[3])
        : "r"(a0), "r"(a1), "r"(a2), "r"(a3), "r"(b0), "r"(b1));
}

// ---------------- setup / graph build ----------------
__global__ void k_setup(const unsigned* __restrict__ eiw) {
    int i = blockIdx.x * 256 + threadIdx.x;
    if (i < NN) { g_cnt[i] = 0; g_pos[i] = 0; }
    if (i < 128) { g_bn1[i] = 0.f; g_bn2[i] = 0.f; }
    if (i == 0) {
        unsigned acc = 0;
        for (int k = 0; k < 128; k++) acc |= eiw[2 * k + 1];
        g_sh = (acc == 0) ? 1 : 0;
    }
}

__global__ void k_degree(const unsigned* __restrict__ eiw) {
    int i = blockIdx.x * 256 + threadIdx.x;
    if (i >= EE) return;
    atomicAdd(&g_cnt[eidx(eiw, (long long)EE + i, g_sh)], 1);
}

__global__ void __launch_bounds__(1024) k_scanrsqrt() {
    __shared__ int ssum[1024];
    const int t = threadIdx.x;
    const int L = (NN + 1023) / 1024;
    int lo = t * L, hi = min(lo + L, NN);
    int s = 0;
    for (int i = lo; i < hi; i++) s += g_cnt[i];
    ssum[t] = s;
    __syncthreads();
    for (int off = 1; off < 1024; off <<= 1) {
        int v = (t >= off) ? ssum[t - off] : 0;
        __syncthreads();
        ssum[t] += v;
        __syncthreads();
    }
    int run = (t == 0) ? 0 : ssum[t - 1];
    for (int i = lo; i < hi; i++) {
        int c = g_cnt[i];
        g_start[i] = run;
        g_deg[i] = rsqrtf(1.0f + (float)c);
        run += c;
    }
}

__global__ void k_fill(const unsigned* __restrict__ eiw) {
    int e = blockIdx.x * 256 + threadIdx.x;
    if (e >= EE) return;
    int sh = g_sh;
    int r = eidx(eiw, e, sh);
    int c = eidx(eiw, (long long)EE + e, sh);
    int p = g_start[c] + atomicAdd(&g_pos[c], 1);
    g_csr[p] = r;
}

// ---------------- fused tf32 encoder ----------------
__global__ void __launch_bounds__(256) k_enc(
        const float* __restrict__ metadata, const float* __restrict__ wf,
        const float* __restrict__ Wm, const float* __restrict__ bm,
        const float* __restrict__ Ww, const float* __restrict__ bw,
        const float* __restrict__ Wc, const float* __restrict__ bc)
{
    __shared__ unsigned SB[128 * 68];
    __shared__ unsigned Wsm[16][68];
#define ASM(r, k) SB[(r) * 20 + (k)]
#define AS2(r, c) SB[(r) * 68 + (c)]

    const int n0 = blockIdx.x * 128;
    const int tid = threadIdx.x;
    const int warp = tid >> 5, lane = tid & 31;
    const int l4 = lane >> 2, lm4 = lane & 3;
    const int rw = warp * 16;

    const float4* Wc4 = reinterpret_cast<const float4*>(Wc);

    float acc2[8][4];
#pragma unroll
    for (int j = 0; j < 8; j++)
#pragma unroll
        for (int i = 0; i < 4; i++) acc2[j][i] = 0.f;

#pragma unroll
    for (int half = 0; half < 2; half++) {
        const float* Ain = half ? wf : metadata;
        const float* W1p = half ? Ww : Wm;
        const float* B1p = half ? bw : bm;
        const int K = half ? 128 : 16;
        const float4* A4 = reinterpret_cast<const float4*>(Ain);
        const float4* W14 = reinterpret_cast<const float4*>(W1p);

        float acc[8][4];
#pragma unroll
        for (int j = 0; j < 8; j++)
#pragma unroll
            for (int i = 0; i < 4; i++) acc[j][i] = 0.f;

        for (int kt = 0; kt < K / 16; kt++) {
#pragma unroll
            for (int it = 0; it < 2; it++) {
                int idx = tid + it * 256;
                int row = idx >> 2, c4 = idx & 3;
                int gn = n0 + row;
                float4 a = make_float4(0.f, 0.f, 0.f, 0.f);
                if (gn < NN) a = A4[gn * (K / 4) + kt * 4 + c4];
                ASM(row, c4 * 4 + 0) = f2tf(a.x);
                ASM(row, c4 * 4 + 1) = f2tf(a.y);
                ASM(row, c4 * 4 + 2) = f2tf(a.z);
                ASM(row, c4 * 4 + 3) = f2tf(a.w);
            }
            {
                int k = tid >> 4, c4 = tid & 15;
                float4 w = W14[(kt * 16 + k) * 16 + c4];
                Wsm[k][c4 * 4 + 0] = f2tf(w.x);
                Wsm[k][c4 * 4 + 1] = f2tf(w.y);
                Wsm[k][c4 * 4 + 2] = f2tf(w.z);
                Wsm[k][c4 * 4 + 3] = f2tf(w.w);
            }
            __syncthreads();
#pragma unroll
            for (int ks = 0; ks < 2; ks++) {
                int kb = ks * 8;
                unsigned a0 = ASM(rw + l4, kb + lm4);
                unsigned a1 = ASM(rw + l4 + 8, kb + lm4);
                unsigned a2 = ASM(rw + l4, kb + lm4 + 4);
                unsigned a3 = ASM(rw + l4 + 8, kb + lm4 + 4);
#pragma unroll
                for (int j = 0; j < 8; j++) {
                    unsigned b0 = Wsm[kb + lm4][j * 8 + l4];
                    unsigned b1 = Wsm[kb + 4 + lm4][j * 8 + l4];
                    mma_tf32(acc[j], a0, a1, a2, a3, b0, b1);
                }
            }
            __syncthreads();
        }

#pragma unroll
        for (int j = 0; j < 8; j++) {
            int cj = j * 8 + lm4 * 2;
            float b0v = B1p[cj], b1v = B1p[cj + 1];
            int r0 = rw + l4, r1 = r0 + 8;
            AS2(r0, cj)     = f2tf(fmaxf(acc[j][0] + b0v, 0.f));
            AS2(r0, cj + 1) = f2tf(fmaxf(acc[j][1] + b1v, 0.f));
            AS2(r1, cj)     = f2tf(fmaxf(acc[j][2] + b0v, 0.f));
            AS2(r1, cj + 1) = f2tf(fmaxf(acc[j][3] + b1v, 0.f));
        }
        __syncthreads();

        for (int kt = 0; kt < 4; kt++) {
            {
                int k = tid >> 4, c4 = tid & 15;
                float4 w = Wc4[(half * 64 + kt * 16 + k) * 16 + c4];
                Wsm[k][c4 * 4 + 0] = f2tf(w.x);
                Wsm[k][c4 * 4 + 1] = f2tf(w.y);
                Wsm[k][c4 * 4 + 2] = f2tf(w.z);
                Wsm[k][c4 * 4 + 3] = f2tf(w.w);
            }
            __syncthreads();
#pragma unroll
            for (int ks = 0; ks < 2; ks++) {
                int ka = kt * 16 + ks * 8;
                int kw = ks * 8;
                unsigned a0 = AS2(rw + l4, ka + lm4);
                unsigned a1 = AS2(rw + l4 + 8, ka + lm4);
                unsigned a2 = AS2(rw + l4, ka + lm4 + 4);
                unsigned a3 = AS2(rw + l4 + 8, ka + lm4 + 4);
#pragma unroll
                for (int j = 0; j < 8; j++) {
                    unsigned b0 = Wsm[kw + lm4][j * 8 + l4];
                    unsigned b1 = Wsm[kw + 4 + lm4][j * 8 + l4];
                    mma_tf32(acc2[j], a0, a1, a2, a3, b0, b1);
                }
            }
            __syncthreads();
        }
    }

    int r0 = n0 + rw + l4;
    int r1 = r0 + 8;
#pragma unroll
    for (int j = 0; j < 8; j++) {
        int cj = j * 8 + lm4 * 2;
        float b0v = bc[cj], b1v = bc[cj + 1];
        if (r0 < NN) {
            float2 v = make_float2(fmaxf(acc2[j][0] + b0v, 0.f),
                                   fmaxf(acc2[j][1] + b1v, 0.f));
            *reinterpret_cast<float2*>(&g_x[r0 * 64 + cj]) = v;
        }
        if (r1 < NN) {
            float2 v = make_float2(fmaxf(acc2[j][2] + b0v, 0.f),
                                   fmaxf(acc2[j][3] + b1v, 0.f));
            *reinterpret_cast<float2*>(&g_x[r1 * 64 + cj]) = v;
        }
    }
#undef ASM
#undef AS2
}

// ---------------- GCN tf32 GEMM (K=64) ----------------
template<int MODE, int SRCB, int OUTB>
__global__ void __launch_bounds__(256) k_gcn_gemm(
        const float* __restrict__ W, const float* __restrict__ bias,
        const float* __restrict__ gamma, const float* __restrict__ beta)
{
    __shared__ unsigned Asm[128][20];
    __shared__ unsigned Wsm[16][68];
    __shared__ float sbn[128];

    const float* A = gbuf<SRCB>();
    float* outb = gbuf<OUTB>();

    const int n0 = blockIdx.x * 128;
    const int tid = threadIdx.x;
    const int warp = tid >> 5, lane = tid & 31;
    const int l4 = lane >> 2, lm4 = lane & 3;
    const int rw = warp * 16;

    if (MODE == 3) {
        if (tid < 64) {
            float s = g_bn1[tid], q = g_bn1[64 + tid];
            float mean = s * (1.0f / NN);
            float var = fmaxf(q * (1.0f / NN) - mean * mean, 0.f);
            float scale = gamma[tid] * rsqrtf(var + BN_EPS);
            sbn[tid] = scale;
            sbn[64 + tid] = beta[tid] - mean * scale;
        }
        __syncthreads();
    }

    float acc[8][4];
#pragma unroll
    for (int j = 0; j < 8; j++)
#pragma unroll
        for (int i = 0; i < 4; i++) acc[j][i] = 0.f;

    const float4* A4 = reinterpret_cast<const float4*>(A);
    const float4* W4 = reinterpret_cast<const float4*>(W);

#pragma unroll
    for (int kt = 0; kt < 4; kt++) {
#pragma unroll
        for (int it = 0; it < 2; it++) {
            int idx = tid + it * 256;
            int row = idx >> 2, c4 = idx & 3;
            int gn = n0 + row;
            float4 a = make_float4(0.f, 0.f, 0.f, 0.f);
            if (gn < NN) {
                a = A4[gn * 16 + kt * 4 + c4];
                if (MODE == 3) {
                    int ch = kt * 16 + c4 * 4;
                    float4 sc = *reinterpret_cast<const float4*>(&sbn[ch]);
                    float4 sv = *reinterpret_cast<const float4*>(&sbn[64 + ch]);
                    a.x = fmaxf(a.x * sc.x + sv.x, 0.f);
                    a.y = fmaxf(a.y * sc.y + sv.y, 0.f);
                    a.z = fmaxf(a.z * sc.z + sv.z, 0.f);
                    a.w = fmaxf(a.w * sc.w + sv.w, 0.f);
                }
            }
            Asm[row][c4 * 4 + 0] = f2tf(a.x);
            Asm[row][c4 * 4 + 1] = f2tf(a.y);
            Asm[row][c4 * 4 + 2] = f2tf(a.z);
            Asm[row][c4 * 4 + 3] = f2tf(a.w);
        }
        {
            int k = tid >> 4, c4 = tid & 15;
            float4 w = W4[(kt * 16 + k) * 16 + c4];
            Wsm[k][c4 * 4 + 0] = f2tf(w.x);
            Wsm[k][c4 * 4 + 1] = f2tf(w.y);
            Wsm[k][c4 * 4 + 2] = f2tf(w.z);
            Wsm[k][c4 * 4 + 3] = f2tf(w.w);
        }
        __syncthreads();
#pragma unroll
        for (int ks = 0; ks < 2; ks++) {
            int kb = ks * 8;
            unsigned a0 = Asm[rw + l4][kb + lm4];
            unsigned a1 = Asm[rw + l4 + 8][kb + lm4];
            unsigned a2 = Asm[rw + l4][kb + lm4 + 4];
            unsigned a3 = Asm[rw + l4 + 8][kb + lm4 + 4];
#pragma unroll
            for (int j = 0; j < 8; j++) {
                unsigned b0 = Wsm[kb + lm4][j * 8 + l4];
                unsigned b1 = Wsm[kb + 4 + lm4][j * 8 + l4];
                mma_tf32(acc[j], a0, a1, a2, a3, b0, b1);
            }
        }
        __syncthreads();
    }

    int r0 = n0 + rw + l4;
    int r1 = r0 + 8;
    float di0 = (r0 < NN) ? g_deg[r0] : 0.f;
    float di1 = (r1 < NN) ? g_deg[r1] : 0.f;
#pragma unroll
    for (int j = 0; j < 8; j++) {
        int cj = j * 8 + lm4 * 2;
        float b0v = bias[cj], b1v = bias[cj + 1];
        if (r0 < NN) {
            float hx = di0 * acc[j][0], hy = di0 * acc[j][1];
            *reinterpret_cast<float2*>(&g_h[r0 * 64 + cj]) = make_float2(hx, hy);
            float ox = b0v + di0 * hx, oy = b1v + di0 * hy;
            if (MODE == 3) {
                float2 ov = *reinterpret_cast<const float2*>(&g_o1[r0 * 64 + cj]);
                ox += fmaxf(ov.x * sbn[cj] + sbn[64 + cj], 0.f);
                oy += fmaxf(ov.y * sbn[cj + 1] + sbn[64 + cj + 1], 0.f);
            }
            *reinterpret_cast<float2*>(&outb[r0 * 64 + cj]) = make_float2(ox, oy);
        }
        if (r1 < NN) {
            float hx = di1 * acc[j][2], hy = di1 * acc[j][3];
            *reinterpret_cast<float2*>(&g_h[r1 * 64 + cj]) = make_float2(hx, hy);
            float ox = b0v + di1 * hx, oy = b1v + di1 * hy;
            if (MODE == 3) {
                float2 ov = *reinterpret_cast<const float2*>(&g_o1[r1 * 64 + cj]);
                ox += fmaxf(ov.x * sbn[cj] + sbn[64 + cj], 0.f);
                oy += fmaxf(ov.y * sbn[cj + 1] + sbn[64 + cj + 1], 0.f);
            }
            *reinterpret_cast<float2*>(&outb[r1 * 64 + cj]) = make_float2(ox, oy);
        }
    }
}

// ---------------- gather + fused BN statistics ----------------
template<int OUTB, int BNB>
__global__ void __launch_bounds__(256) k_gatherbn()
{
    __shared__ float4 ss[256];
    __shared__ float4 sq[256];
    int tid = threadIdx.x;
    int idx = blockIdx.x * 256 + tid;
    int node = idx >> 4;
    int sub = idx & 15;
    float4 o = make_float4(0.f, 0.f, 0.f, 0.f);
    if (node < NN) {
        int j = g_start[node];
        int end = j + g_cnt[node];
        const float4* hs4 = reinterpret_cast<const float4*>(g_h);
        float4 acc = make_float4(0.f, 0.f, 0.f, 0.f);
        for (; j + 4 <= end; j += 4) {
            int r0 = g_csr[j], r1 = g_csr[j + 1], r2 = g_csr[j + 2], r3 = g_csr[j + 3];
            float4 v0 = hs4[r0 * 16 + sub];
            float4 v1 = hs4[r1 * 16 + sub];
            float4 v2 = hs4[r2 * 16 + sub];
            float4 v3 = hs4[r3 * 16 + sub];
            acc.x += (v0.x + v1.x) + (v2.x + v3.x);
            acc.y += (v0.y + v1.y) + (v2.y + v3.y);
            acc.z += (v0.z + v1.z) + (v2.z + v3.z);
            acc.w += (v0.w + v1.w) + (v2.w + v3.w);
        }
        for (; j < end; j++) {
            float4 v = hs4[g_csr[j] * 16 + sub];
            acc.x += v.x; acc.y += v.y; acc.z += v.z; acc.w += v.w;
        }
        float dc = g_deg[node];
        float4* out4 = reinterpret_cast<float4*>(gbuf<OUTB>());
        o = out4[node * 16 + sub];
        o.x += dc * acc.x; o.y += dc * acc.y; o.z += dc * acc.z; o.w += dc * acc.w;
        out4[node * 16 + sub] = o;
    }
    ss[tid] = o;
    sq[tid] = make_float4(o.x * o.x, o.y * o.y, o.z * o.z, o.w * o.w);
    __syncthreads();
#pragma unroll
    for (int off = 128; off >= 16; off >>= 1) {
        if (tid < off) {
            float4 a = ss[tid], b = ss[tid + off];
            a.x += b.x; a.y += b.y; a.z += b.z; a.w += b.w;
            ss[tid] = a;
            float4 c = sq[tid], d = sq[tid + off];
            c.x += d.x; c.y += d.y; c.z += d.z; c.w += d.w;
            sq[tid] = c;
        }
        __syncthreads();
    }
    if (tid < 16) {
        float* sums = gbn<BNB>();
        float4 a = ss[tid], c = sq[tid];
        atomicAdd(&sums[tid * 4 + 0], a.x); atomicAdd(&sums[tid * 4 + 1], a.y);
        atomicAdd(&sums[tid * 4 + 2], a.z); atomicAdd(&sums[tid * 4 + 3], a.w);
        atomicAdd(&sums[64 + tid * 4 + 0], c.x); atomicAdd(&sums[64 + tid * 4 + 1], c.y);
        atomicAdd(&sums[64 + tid * 4 + 2], c.z); atomicAdd(&sums[64 + tid * 4 + 3], c.w);
    }
}

// ---------------- pool + heads ----------------
__device__ __forceinline__ int lbound(const unsigned* __restrict__ bw, long long v, int sh) {
    int lo = 0, hi = NN;
    while (lo < hi) {
        int mid = (lo + hi) >> 1;
        long long bv = (long long)bw[(long long)mid << sh];
        if (bv < v) lo = mid + 1; else hi = mid;
    }
    return lo;
}

__global__ void __launch_bounds__(256) k_poolheads(const unsigned* __restrict__ bw,
        const float* __restrict__ g2, const float* __restrict__ be2,
        const float* __restrict__ Wa1, const float* __restrict__ ba1,
        const float* __restrict__ Wa2, const float* __restrict__ ba2,
        const float* __restrict__ Wo1, const float* __restrict__ bo1,
        const float* __restrict__ Wo2, const float* __restrict__ bo2,
        float* __restrict__ outp)
{
    __shared__ float sbn[128];
    __shared__ float ssum[16][64];
    __shared__ float smax[16][64];
    __shared__ float sxc[128];
    const int tid = threadIdx.x;
    const int g = blockIdx.x;

    if (tid < 64) {
        float s = g_bn2[tid], q = g_bn2[64 + tid];
        float mean = s * (1.0f / NN);
        float var = fmaxf(q * (1.0f / NN) - mean * mean, 0.f);
        float scale = g2[tid] * rsqrtf(var + BN_EPS);
        sbn[tid] = scale;
        sbn[64 + tid] = be2[tid] - mean * scale;
    }
    __syncthreads();

    const float4* X = reinterpret_cast<const float4*>(g_o2);
    int sh0 = g_sh;
    int start = lbound(bw, (long long)g, sh0);
    int end   = lbound(bw, (long long)g + 1, sh0);
    int cc = tid & 15;
    int chan = cc * 4;
    int rg = tid >> 4;
    float4 sc = *reinterpret_cast<const float4*>(&sbn[chan]);
    float4 sv = *reinterpret_cast<const float4*>(&sbn[64 + chan]);
    float4 s = make_float4(0.f, 0.f, 0.f, 0.f);
    float4 m = make_float4(0.f, 0.f, 0.f, 0.f);
    for (int n = start + rg; n < end; n += 16) {
        float4 v = X[n * 16 + cc];
        v.x = fmaxf(v.x * sc.x + sv.x, 0.f);
        v.y = fmaxf(v.y * sc.y + sv.y, 0.f);
        v.z = fmaxf(v.z * sc.z + sv.z, 0.f);
        v.w = fmaxf(v.w * sc.w + sv.w, 0.f);
        s.x += v.x; s.y += v.y; s.z += v.z; s.w += v.w;
        m.x = fmaxf(m.x, v.x); m.y = fmaxf(m.y, v.y);
        m.z = fmaxf(m.z, v.z); m.w = fmaxf(m.w, v.w);
    }
    *reinterpret_cast<float4*>(&ssum[rg][chan]) = s;
    *reinterpret_cast<float4*>(&smax[rg][chan]) = m;
    __syncthreads();
    for (int off = 8; off >= 1; off >>= 1) {
        if (rg < off) {
            float4 a  = *reinterpret_cast<float4*>(&ssum[rg][chan]);
            float4 b  = *reinterpret_cast<float4*>(&ssum[rg + off][chan]);
            a.x += b.x; a.y += b.y; a.z += b.z; a.w += b.w;
            *reinterpret_cast<float4*>(&ssum[rg][chan]) = a;
            float4 am = *reinterpret_cast<float4*>(&smax[rg][chan]);
            float4 bm = *reinterpret_cast<float4*>(&smax[rg + off][chan]);
            am.x = fmaxf(am.x, bm.x); am.y = fmaxf(am.y, bm.y);
            am.z = fmaxf(am.z, bm.z); am.w = fmaxf(am.w, bm.w);
            *reinterpret_cast<float4*>(&smax[rg][chan]) = am;
        }
        __syncthreads();
    }
    if (rg == 0) {
        float inv = 1.0f / fmaxf((float)(end - start), 1.0f);
        float4 a = *reinterpret_cast<float4*>(&ssum[0][chan]);
        sxc[chan + 0] = a.x * inv; sxc[chan + 1] = a.y * inv;
        sxc[chan + 2] = a.z * inv; sxc[chan + 3] = a.w * inv;
        float4 mm = *reinterpret_cast<float4*>(&smax[0][chan]);
        sxc[64 + chan + 0] = mm.x; sxc[64 + chan + 1] = mm.y;
        sxc[64 + chan + 2] = mm.z; sxc[64 + chan + 3] = mm.w;
    }
    __syncthreads();

    int wid = tid >> 5;
    if (wid < 2) {
        int lane = tid & 31;
        int head = wid;
        const float* W1p = head ? Wo1 : Wa1;
        const float* b1p = head ? bo1 : ba1;
        const float* W2p = head ? Wo2 : Wa2;
        const float* b2p = head ? bo2 : ba2;
        float a0 = b1p[lane], a1 = b1p[lane + 32];
#pragma unroll 4
        for (int k = 0; k < 128; k++) {
            float v = sxc[k];
            a0 += v * W1p[k * 64 + lane];
            a1 += v * W1p[k * 64 + lane + 32];
        }
        a0 = fmaxf(a0, 0.f); a1 = fmaxf(a1, 0.f);
        float o = a0 * W2p[lane] + a1 * W2p[lane + 32];
#pragma unroll
        for (int off = 16; off; off >>= 1) o += __shfl_xor_sync(0xffffffffu, o, off);
        if (lane == 0) outp[head * GG + g] = o + b2p[0];
    }
}

// ---------------- launch (2-stream overlap, capture-safe fork/join) ----------------
extern "C" void kernel_launch(void* const* d_in, const int* in_sizes, int n_in,
                              void* d_out, int out_size)
{
    const float*    metadata = (const float*)d_in[0];
    const float*    wf       = (const float*)d_in[1];
    const unsigned* eiw      = (const unsigned*)d_in[2];
    const unsigned* batchw   = (const unsigned*)d_in[3];
    const float* Wm  = (const float*)d_in[4];
    const float* bm  = (const float*)d_in[5];
    const float* Ww  = (const float*)d_in[6];
    const float* bw  = (const float*)d_in[7];
    const float* Wc  = (const float*)d_in[8];
    const float* bc  = (const float*)d_in[9];
    const float* W1  = (const float*)d_in[10];
    const float* b1  = (const float*)d_in[11];
    const float* W2  = (const float*)d_in[12];
    const float* b2  = (const float*)d_in[13];
    const float* g1  = (const float*)d_in[14];
    const float* be1 = (const float*)d_in[15];
    const float* g2  = (const float*)d_in[16];
    const float* be2 = (const float*)d_in[17];
    const float* Wla1 = (const float*)d_in[18];
    const float* bla1 = (const float*)d_in[19];
    const float* Wla2 = (const float*)d_in[20];
    const float* bla2 = (const float*)d_in[21];
    const float* Wlo1 = (const float*)d_in[22];
    const float* blo1 = (const float*)d_in[23];
    const float* Wlo2 = (const float*)d_in[24];
    const float* blo2 = (const float*)d_in[25];
    float* outp = (float*)d_out;

    const int NB = (NN + 255) / 256;
    const int EB = (EE + 255) / 256;
    const int GB = (NN + 127) / 128;          // 391
    const int AB = (NN * 16 + 255) / 256;     // 3125

    // one-time creation (happens on the non-captured correctness call)
    static cudaStream_t s1 = nullptr;
    static cudaEvent_t ev0 = nullptr, ev_scan = nullptr, ev_g1 = nullptr;
    if (s1 == nullptr) {
        cudaStreamCreateWithFlags(&s1, cudaStreamNonBlocking);
        cudaEventCreateWithFlags(&ev0, cudaEventDisableTiming);
        cudaEventCreateWithFlags(&ev_scan, cudaEventDisableTiming);
        cudaEventCreateWithFlags(&ev_g1, cudaEventDisableTiming);
    }

    // fork point
    cudaEventRecord(ev0, 0);
    cudaStreamWaitEvent(s1, ev0, 0);

    // stream 0: graph build
    k_setup<<<NB, 256>>>(eiw);
    k_degree<<<EB, 256>>>(eiw);
    k_scanrsqrt<<<1, 1024>>>();
    cudaEventRecord(ev_scan, 0);
    k_fill<<<EB, 256>>>(eiw);

    // stream 1: encoder (independent), then GEMM1 after deg ready
    k_enc<<<GB, 256, 0, s1>>>(metadata, wf, Wm, bm, Ww, bw, Wc, bc);
    cudaStreamWaitEvent(s1, ev_scan, 0);
    k_gcn_gemm<1, 1, 4><<<GB, 256, 0, s1>>>(W1, b1, nullptr, nullptr);
    cudaEventRecord(ev_g1, s1);

    // join: gather1 needs fill (stream order) + gemm1 (event)
    cudaStreamWaitEvent(0, ev_g1, 0);
    k_gatherbn<4, 0><<<AB, 256>>>();

    k_gcn_gemm<3, 4, 5><<<GB, 256>>>(W2, b2, g1, be1);
    k_gatherbn<5, 1><<<AB, 256>>>();

    k_poolheads<<<GG, 256>>>(batchw, g2, be2,
                             Wla1, bla1, Wla2, bla2, Wlo1, blo1, Wlo2, blo2, outp);
}

// round 15
// speedup vs baseline: 1.1749x; 1.0283x over previous
#include <cuda_runtime.h>

#define NN 50000
#define EE 800000
#define GG 128
#define BN_EPS 1e-5f

// ---------------- scratch ----------------
__device__ float g_deg[NN];
__device__ int   g_cnt[NN];
__device__ int   g_pos[NN];
__device__ int   g_start[NN];
__device__ int   g_csr[EE];
__device__ float g_x[NN * 64];
__device__ float g_h[NN * 64];
__device__ float g_o1[NN * 64];
__device__ float g_o2[NN * 64];
__device__ float g_bn1[128];
__device__ float g_bn2[128];
__device__ int   g_sh;

template<int ID> __device__ __forceinline__ float* gbuf() {
    if (ID == 1) return g_x;
    if (ID == 4) return g_o1;
    if (ID == 5) return g_o2;
    return nullptr;
}
template<int ID> __device__ __forceinline__ float* gbn() {
    return (ID == 0) ? g_bn1 : g_bn2;
}

__device__ __forceinline__ int eidx(const unsigned* __restrict__ w, long long elem, int sh) {
    int v = (int)w[elem << sh];
    v = v < 0 ? 0 : v;
    return v >= NN ? NN - 1 : v;
}

__device__ __forceinline__ unsigned f2tf(float f) {
    unsigned u; asm("cvt.rna.tf32.f32 %0, %1;" : "=r"(u) : "f"(f)); return u;
}

__device__ __forceinline__ void mma_tf32(float* c, unsigned a0, unsigned a1,
                                         unsigned a2, unsigned a3,
                                         unsigned b0, unsigned b1) {
    asm volatile(
        "mma.sync.aligned.m16n8k8.row.col.f32.tf32.tf32.f32 "
        "{%0,%1,%2,%3}, {%4,%5,%6,%7}, {%8,%9}, {%0,%1,%2,%3};\n"
        : "+f"(c[0]), "+f"(c[1]), "+f"(c[2]), "+f"(c[3])
        : "r"(a0), "r"(a1), "r"(a2), "r"(a3), "r"(b0), "r"(b1));
}

// ---------------- setup / graph build ----------------
__global__ void k_setup(const unsigned* __restrict__ eiw) {
    int i = blockIdx.x * 256 + threadIdx.x;
    if (i < NN) { g_cnt[i] = 0; g_pos[i] = 0; }
    if (i < 128) { g_bn1[i] = 0.f; g_bn2[i] = 0.f; }
    if (i == 0) {
        unsigned acc = 0;
        for (int k = 0; k < 128; k++) acc |= eiw[2 * k + 1];
        g_sh = (acc == 0) ? 1 : 0;
    }
}

__global__ void k_degree(const unsigned* __restrict__ eiw) {
    int i = blockIdx.x * 256 + threadIdx.x;
    if (i >= EE) return;
    atomicAdd(&g_cnt[eidx(eiw, (long long)EE + i, g_sh)], 1);
}

__global__ void __launch_bounds__(1024) k_scanrsqrt() {
    __shared__ int ssum[1024];
    const int t = threadIdx.x;
    const int L = (NN + 1023) / 1024;
    int lo = t * L, hi = min(lo + L, NN);
    int s = 0;
    for (int i = lo; i < hi; i++) s += g_cnt[i];
    ssum[t] = s;
    __syncthreads();
    for (int off = 1; off < 1024; off <<= 1) {
        int v = (t >= off) ? ssum[t - off] : 0;
        __syncthreads();
        ssum[t] += v;
        __syncthreads();
    }
    int run = (t == 0) ? 0 : ssum[t - 1];
    for (int i = lo; i < hi; i++) {
        int c = g_cnt[i];
        g_start[i] = run;
        g_deg[i] = rsqrtf(1.0f + (float)c);
        run += c;
    }
}

__global__ void k_fill(const unsigned* __restrict__ eiw) {
    int e = blockIdx.x * 256 + threadIdx.x;
    if (e >= EE) return;
    int sh = g_sh;
    int r = eidx(eiw, e, sh);
    int c = eidx(eiw, (long long)EE + e, sh);
    int p = g_start[c] + atomicAdd(&g_pos[c], 1);
    g_csr[p] = r;
}

// ---------------- fused tf32 encoder ----------------
__global__ void __launch_bounds__(256) k_enc(
        const float* __restrict__ metadata, const float* __restrict__ wf,
        const float* __restrict__ Wm, const float* __restrict__ bm,
        const float* __restrict__ Ww, const float* __restrict__ bw,
        const float* __restrict__ Wc, const float* __restrict__ bc)
{
    __shared__ unsigned SB[128 * 68];
    __shared__ unsigned Wsm[16][68];
#define ASM(r, k) SB[(r) * 20 + (k)]
#define AS2(r, c) SB[(r) * 68 + (c)]

    const int n0 = blockIdx.x * 128;
    const int tid = threadIdx.x;
    const int warp = tid >> 5, lane = tid & 31;
    const int l4 = lane >> 2, lm4 = lane & 3;
    const int rw = warp * 16;

    const float4* Wc4 = reinterpret_cast<const float4*>(Wc);

    float acc2[8][4];
#pragma unroll
    for (int j = 0; j < 8; j++)
#pragma unroll
        for (int i = 0; i < 4; i++) acc2[j][i] = 0.f;

#pragma unroll
    for (int half = 0; half < 2; half++) {
        const float* Ain = half ? wf : metadata;
        const float* W1p = half ? Ww : Wm;
        const float* B1p = half ? bw : bm;
        const int K = half ? 128 : 16;
        const float4* A4 = reinterpret_cast<const float4*>(Ain);
        const float4* W14 = reinterpret_cast<const float4*>(W1p);

        float acc[8][4];
#pragma unroll
        for (int j = 0; j < 8; j++)
#pragma unroll
            for (int i = 0; i < 4; i++) acc[j][i] = 0.f;

        for (int kt = 0; kt < K / 16; kt++) {
#pragma unroll
            for (int it = 0; it < 2; it++) {
                int idx = tid + it * 256;
                int row = idx >> 2, c4 = idx & 3;
                int gn = n0 + row;
                float4 a = make_float4(0.f, 0.f, 0.f, 0.f);
                if (gn < NN) a = A4[gn * (K / 4) + kt * 4 + c4];
                ASM(row, c4 * 4 + 0) = f2tf(a.x);
                ASM(row, c4 * 4 + 1) = f2tf(a.y);
                ASM(row, c4 * 4 + 2) = f2tf(a.z);
                ASM(row, c4 * 4 + 3) = f2tf(a.w);
            }
            {
                int k = tid >> 4, c4 = tid & 15;
                float4 w = W14[(kt * 16 + k) * 16 + c4];
                Wsm[k][c4 * 4 + 0] = f2tf(w.x);
                Wsm[k][c4 * 4 + 1] = f2tf(w.y);
                Wsm[k][c4 * 4 + 2] = f2tf(w.z);
                Wsm[k][c4 * 4 + 3] = f2tf(w.w);
            }
            __syncthreads();
#pragma unroll
            for (int ks = 0; ks < 2; ks++) {
                int kb = ks * 8;
                unsigned a0 = ASM(rw + l4, kb + lm4);
                unsigned a1 = ASM(rw + l4 + 8, kb + lm4);
                unsigned a2 = ASM(rw + l4, kb + lm4 + 4);
                unsigned a3 = ASM(rw + l4 + 8, kb + lm4 + 4);
#pragma unroll
                for (int j = 0; j < 8; j++) {
                    unsigned b0 = Wsm[kb + lm4][j * 8 + l4];
                    unsigned b1 = Wsm[kb + 4 + lm4][j * 8 + l4];
                    mma_tf32(acc[j], a0, a1, a2, a3, b0, b1);
                }
            }
            __syncthreads();
        }

#pragma unroll
        for (int j = 0; j < 8; j++) {
            int cj = j * 8 + lm4 * 2;
            float b0v = B1p[cj], b1v = B1p[cj + 1];
            int r0 = rw + l4, r1 = r0 + 8;
            AS2(r0, cj)     = f2tf(fmaxf(acc[j][0] + b0v, 0.f));
            AS2(r0, cj + 1) = f2tf(fmaxf(acc[j][1] + b1v, 0.f));
            AS2(r1, cj)     = f2tf(fmaxf(acc[j][2] + b0v, 0.f));
            AS2(r1, cj + 1) = f2tf(fmaxf(acc[j][3] + b1v, 0.f));
        }
        __syncthreads();

        for (int kt = 0; kt < 4; kt++) {
            {
                int k = tid >> 4, c4 = tid & 15;
                float4 w = Wc4[(half * 64 + kt * 16 + k) * 16 + c4];
                Wsm[k][c4 * 4 + 0] = f2tf(w.x);
                Wsm[k][c4 * 4 + 1] = f2tf(w.y);
                Wsm[k][c4 * 4 + 2] = f2tf(w.z);
                Wsm[k][c4 * 4 + 3] = f2tf(w.w);
            }
            __syncthreads();
#pragma unroll
            for (int ks = 0; ks < 2; ks++) {
                int ka = kt * 16 + ks * 8;
                int kw = ks * 8;
                unsigned a0 = AS2(rw + l4, ka + lm4);
                unsigned a1 = AS2(rw + l4 + 8, ka + lm4);
                unsigned a2 = AS2(rw + l4, ka + lm4 + 4);
                unsigned a3 = AS2(rw + l4 + 8, ka + lm4 + 4);
#pragma unroll
                for (int j = 0; j < 8; j++) {
                    unsigned b0 = Wsm[kw + lm4][j * 8 + l4];
                    unsigned b1 = Wsm[kw + 4 + lm4][j * 8 + l4];
                    mma_tf32(acc2[j], a0, a1, a2, a3, b0, b1);
                }
            }
            __syncthreads();
        }
    }

    int r0 = n0 + rw + l4;
    int r1 = r0 + 8;
#pragma unroll
    for (int j = 0; j < 8; j++) {
        int cj = j * 8 + lm4 * 2;
        float b0v = bc[cj], b1v = bc[cj + 1];
        if (r0 < NN) {
            float2 v = make_float2(fmaxf(acc2[j][0] + b0v, 0.f),
                                   fmaxf(acc2[j][1] + b1v, 0.f));
            *reinterpret_cast<float2*>(&g_x[r0 * 64 + cj]) = v;
        }
        if (r1 < NN) {
            float2 v = make_float2(fmaxf(acc2[j][2] + b0v, 0.f),
                                   fmaxf(acc2[j][3] + b1v, 0.f));
            *reinterpret_cast<float2*>(&g_x[r1 * 64 + cj]) = v;
        }
    }
#undef ASM
#undef AS2
}

// ---------------- GCN tf32 GEMM (K=64): writes ONLY g_h = dinv*(A@W) ----------------
// MODE 1: A = g_x
// MODE 3: A = relu(bn1(o1)) (bnfin from raw sums in-block)
template<int MODE, int SRCB>
__global__ void __launch_bounds__(256) k_gcn_gemm(
        const float* __restrict__ W,
        const float* __restrict__ gamma, const float* __restrict__ beta)
{
    __shared__ unsigned Asm[128][20];
    __shared__ unsigned Wsm[16][68];
    __shared__ float sbn[128];

    const float* A = gbuf<SRCB>();

    const int n0 = blockIdx.x * 128;
    const int tid = threadIdx.x;
    const int warp = tid >> 5, lane = tid & 31;
    const int l4 = lane >> 2, lm4 = lane & 3;
    const int rw = warp * 16;

    if (MODE == 3) {
        if (tid < 64) {
            float s = g_bn1[tid], q = g_bn1[64 + tid];
            float mean = s * (1.0f / NN);
            float var = fmaxf(q * (1.0f / NN) - mean * mean, 0.f);
            float scale = gamma[tid] * rsqrtf(var + BN_EPS);
            sbn[tid] = scale;
            sbn[64 + tid] = beta[tid] - mean * scale;
        }
        __syncthreads();
    }

    float acc[8][4];
#pragma unroll
    for (int j = 0; j < 8; j++)
#pragma unroll
        for (int i = 0; i < 4; i++) acc[j][i] = 0.f;

    const float4* A4 = reinterpret_cast<const float4*>(A);
    const float4* W4 = reinterpret_cast<const float4*>(W);

#pragma unroll
    for (int kt = 0; kt < 4; kt++) {
#pragma unroll
        for (int it = 0; it < 2; it++) {
            int idx = tid + it * 256;
            int row = idx >> 2, c4 = idx & 3;
            int gn = n0 + row;
            float4 a = make_float4(0.f, 0.f, 0.f, 0.f);
            if (gn < NN) {
                a = A4[gn * 16 + kt * 4 + c4];
                if (MODE == 3) {
                    int ch = kt * 16 + c4 * 4;
                    float4 sc = *reinterpret_cast<const float4*>(&sbn[ch]);
                    float4 sv = *reinterpret_cast<const float4*>(&sbn[64 + ch]);
                    a.x = fmaxf(a.x * sc.x + sv.x, 0.f);
                    a.y = fmaxf(a.y * sc.y + sv.y, 0.f);
                    a.z = fmaxf(a.z * sc.z + sv.z, 0.f);
                    a.w = fmaxf(a.w * sc.w + sv.w, 0.f);
                }
            }
            Asm[row][c4 * 4 + 0] = f2tf(a.x);
            Asm[row][c4 * 4 + 1] = f2tf(a.y);
            Asm[row][c4 * 4 + 2] = f2tf(a.z);
            Asm[row][c4 * 4 + 3] = f2tf(a.w);
        }
        {
            int k = tid >> 4, c4 = tid & 15;
            float4 w = W4[(kt * 16 + k) * 16 + c4];
            Wsm[k][c4 * 4 + 0] = f2tf(w.x);
            Wsm[k][c4 * 4 + 1] = f2tf(w.y);
            Wsm[k][c4 * 4 + 2] = f2tf(w.z);
            Wsm[k][c4 * 4 + 3] = f2tf(w.w);
        }
        __syncthreads();
#pragma unroll
        for (int ks = 0; ks < 2; ks++) {
            int kb = ks * 8;
            unsigned a0 = Asm[rw + l4][kb + lm4];
            unsigned a1 = Asm[rw + l4 + 8][kb + lm4];
            unsigned a2 = Asm[rw + l4][kb + lm4 + 4];
            unsigned a3 = Asm[rw + l4 + 8][kb + lm4 + 4];
#pragma unroll
            for (int j = 0; j < 8; j++) {
                unsigned b0 = Wsm[kb + lm4][j * 8 + l4];
                unsigned b1 = Wsm[kb + 4 + lm4][j * 8 + l4];
                mma_tf32(acc[j], a0, a1, a2, a3, b0, b1);
            }
        }
        __syncthreads();
    }

    int r0 = n0 + rw + l4;
    int r1 = r0 + 8;
    float di0 = (r0 < NN) ? g_deg[r0] : 0.f;
    float di1 = (r1 < NN) ? g_deg[r1] : 0.f;
#pragma unroll
    for (int j = 0; j < 8; j++) {
        int cj = j * 8 + lm4 * 2;
        if (r0 < NN)
            *reinterpret_cast<float2*>(&g_h[r0 * 64 + cj]) =
                make_float2(di0 * acc[j][0], di0 * acc[j][1]);
        if (r1 < NN)
            *reinterpret_cast<float2*>(&g_h[r1 * 64 + cj]) =
                make_float2(di1 * acc[j][2], di1 * acc[j][3]);
    }
}

// ---------------- gather (pipelined) + seed + BN statistics ----------------
// LAYER 1: o = b + dc*(hs_self + Σ hs_r)
// LAYER 2: o = b + dc*(hs_self + Σ hs_r) + relu(bn1(o1))
template<int OUTB, int BNB, int LAYER>
__global__ void __launch_bounds__(256) k_gatherbn(
        const float* __restrict__ bias,
        const float* __restrict__ gamma, const float* __restrict__ beta)
{
    __shared__ float4 ss[256];
    __shared__ float4 sq[256];
    __shared__ float sbn[128];
    int tid = threadIdx.x;

    if (LAYER == 2) {
        if (tid < 64) {
            float s = g_bn1[tid], q = g_bn1[64 + tid];
            float mean = s * (1.0f / NN);
            float var = fmaxf(q * (1.0f / NN) - mean * mean, 0.f);
            float scale = gamma[tid] * rsqrtf(var + BN_EPS);
            sbn[tid] = scale;
            sbn[64 + tid] = beta[tid] - mean * scale;
        }
        __syncthreads();
    }

    int idx = blockIdx.x * 256 + tid;
    int node = idx >> 4;
    int sub = idx & 15;
    float4 o = make_float4(0.f, 0.f, 0.f, 0.f);
    if (node < NN) {
        const float4* hs4 = reinterpret_cast<const float4*>(g_h);
        float4 acc = hs4[node * 16 + sub];   // self contribution
        int j = g_start[node];
        int end = j + g_cnt[node];
        // software-pipelined 4-wide walk: prefetch next indices during value loads
        if (j + 4 <= end) {
            int r0 = g_csr[j], r1 = g_csr[j + 1], r2 = g_csr[j + 2], r3 = g_csr[j + 3];
            j += 4;
            for (; j + 4 <= end; j += 4) {
                int n0 = g_csr[j], n1 = g_csr[j + 1], n2 = g_csr[j + 2], n3 = g_csr[j + 3];
                float4 v0 = hs4[r0 * 16 + sub];
                float4 v1 = hs4[r1 * 16 + sub];
                float4 v2 = hs4[r2 * 16 + sub];
                float4 v3 = hs4[r3 * 16 + sub];
                acc.x += (v0.x + v1.x) + (v2.x + v3.x);
                acc.y += (v0.y + v1.y) + (v2.y + v3.y);
                acc.z += (v0.z + v1.z) + (v2.z + v3.z);
                acc.w += (v0.w + v1.w) + (v2.w + v3.w);
                r0 = n0; r1 = n1; r2 = n2; r3 = n3;
            }
            float4 v0 = hs4[r0 * 16 + sub];
            float4 v1 = hs4[r1 * 16 + sub];
            float4 v2 = hs4[r2 * 16 + sub];
            float4 v3 = hs4[r3 * 16 + sub];
            acc.x += (v0.x + v1.x) + (v2.x + v3.x);
            acc.y += (v0.y + v1.y) + (v2.y + v3.y);
            acc.z += (v0.z + v1.z) + (v2.z + v3.z);
            acc.w += (v0.w + v1.w) + (v2.w + v3.w);
        }
        for (; j < end; j++) {
            float4 v = hs4[g_csr[j] * 16 + sub];
            acc.x += v.x; acc.y += v.y; acc.z += v.z; acc.w += v.w;
        }
        float dc = g_deg[node];
        int chan = sub * 4;
        float4 b4 = *reinterpret_cast<const float4*>(&bias[chan]);
        o.x = b4.x + dc * acc.x; o.y = b4.y + dc * acc.y;
        o.z = b4.z + dc * acc.z; o.w = b4.w + dc * acc.w;
        if (LAYER == 2) {
            float4 ov = *reinterpret_cast<const float4*>(&g_o1[node * 64 + chan]);
            float4 sc = *reinterpret_cast<const float4*>(&sbn[chan]);
            float4 sv = *reinterpret_cast<const float4*>(&sbn[64 + chan]);
            o.x += fmaxf(ov.x * sc.x + sv.x, 0.f);
            o.y += fmaxf(ov.y * sc.y + sv.y, 0.f);
            o.z += fmaxf(ov.z * sc.z + sv.z, 0.f);
            o.w += fmaxf(ov.w * sc.w + sv.w, 0.f);
        }
        reinterpret_cast<float4*>(gbuf<OUTB>())[node * 16 + sub] = o;
    }
    ss[tid] = o;
    sq[tid] = make_float4(o.x * o.x, o.y * o.y, o.z * o.z, o.w * o.w);
    __syncthreads();
#pragma unroll
    for (int off = 128; off >= 16; off >>= 1) {
        if (tid < off) {
            float4 a = ss[tid], b = ss[tid + off];
            a.x += b.x; a.y += b.y; a.z += b.z; a.w += b.w;
            ss[tid] = a;
            float4 c = sq[tid], d = sq[tid + off];
            c.x += d.x; c.y += d.y; c.z += d.z; c.w += d.w;
            sq[tid] = c;
        }
        __syncthreads();
    }
    if (tid < 16) {
        float* sums = gbn<BNB>();
        float4 a = ss[tid], c = sq[tid];
        atomicAdd(&sums[tid * 4 + 0], a.x); atomicAdd(&sums[tid * 4 + 1], a.y);
        atomicAdd(&sums[tid * 4 + 2], a.z); atomicAdd(&sums[tid * 4 + 3], a.w);
        atomicAdd(&sums[64 + tid * 4 + 0], c.x); atomicAdd(&sums[64 + tid * 4 + 1], c.y);
        atomicAdd(&sums[64 + tid * 4 + 2], c.z); atomicAdd(&sums[64 + tid * 4 + 3], c.w);
    }
}

// ---------------- pool + heads ----------------
__device__ __forceinline__ int lbound(const unsigned* __restrict__ bw, long long v, int sh) {
    int lo = 0, hi = NN;
    while (lo < hi) {
        int mid = (lo + hi) >> 1;
        long long bv = (long long)bw[(long long)mid << sh];
        if (bv < v) lo = mid + 1; else hi = mid;
    }
    return lo;
}

__global__ void __launch_bounds__(256) k_poolheads(const unsigned* __restrict__ bw,
        const float* __restrict__ g2, const float* __restrict__ be2,
        const float* __restrict__ Wa1, const float* __restrict__ ba1,
        const float* __restrict__ Wa2, const float* __restrict__ ba2,
        const float* __restrict__ Wo1, const float* __restrict__ bo1,
        const float* __restrict__ Wo2, const float* __restrict__ bo2,
        float* __restrict__ outp)
{
    __shared__ float sbn[128];
    __shared__ float ssum[16][64];
    __shared__ float smax[16][64];
    __shared__ float sxc[128];
    const int tid = threadIdx.x;
    const int g = blockIdx.x;

    if (tid < 64) {
        float s = g_bn2[tid], q = g_bn2[64 + tid];
        float mean = s * (1.0f / NN);
        float var = fmaxf(q * (1.0f / NN) - mean * mean, 0.f);
        float scale = g2[tid] * rsqrtf(var + BN_EPS);
        sbn[tid] = scale;
        sbn[64 + tid] = be2[tid] - mean * scale;
    }
    __syncthreads();

    const float4* X = reinterpret_cast<const float4*>(g_o2);
    int sh0 = g_sh;
    int start = lbound(bw, (long long)g, sh0);
    int end   = lbound(bw, (long long)g + 1, sh0);
    int cc = tid & 15;
    int chan = cc * 4;
    int rg = tid >> 4;
    float4 sc = *reinterpret_cast<const float4*>(&sbn[chan]);
    float4 sv = *reinterpret_cast<const float4*>(&sbn[64 + chan]);
    float4 s = make_float4(0.f, 0.f, 0.f, 0.f);
    float4 m = make_float4(0.f, 0.f, 0.f, 0.f);
    for (int n = start + rg; n < end; n += 16) {
        float4 v = X[n * 16 + cc];
        v.x = fmaxf(v.x * sc.x + sv.x, 0.f);
        v.y = fmaxf(v.y * sc.y + sv.y, 0.f);
        v.z = fmaxf(v.z * sc.z + sv.z, 0.f);
        v.w = fmaxf(v.w * sc.w + sv.w, 0.f);
        s.x += v.x; s.y += v.y; s.z += v.z; s.w += v.w;
        m.x = fmaxf(m.x, v.x); m.y = fmaxf(m.y, v.y);
        m.z = fmaxf(m.z, v.z); m.w = fmaxf(m.w, v.w);
    }
    *reinterpret_cast<float4*>(&ssum[rg][chan]) = s;
    *reinterpret_cast<float4*>(&smax[rg][chan]) = m;
    __syncthreads();
    for (int off = 8; off >= 1; off >>= 1) {
        if (rg < off) {
            float4 a  = *reinterpret_cast<float4*>(&ssum[rg][chan]);
            float4 b  = *reinterpret_cast<float4*>(&ssum[rg + off][chan]);
            a.x += b.x; a.y += b.y; a.z += b.z; a.w += b.w;
            *reinterpret_cast<float4*>(&ssum[rg][chan]) = a;
            float4 am = *reinterpret_cast<float4*>(&smax[rg][chan]);
            float4 bm = *reinterpret_cast<float4*>(&smax[rg + off][chan]);
            am.x = fmaxf(am.x, bm.x); am.y = fmaxf(am.y, bm.y);
            am.z = fmaxf(am.z, bm.z); am.w = fmaxf(am.w, bm.w);
            *reinterpret_cast<float4*>(&smax[rg][chan]) = am;
        }
        __syncthreads();
    }
    if (rg == 0) {
        float inv = 1.0f / fmaxf((float)(end - start), 1.0f);
        float4 a = *reinterpret_cast<float4*>(&ssum[0][chan]);
        sxc[chan + 0] = a.x * inv; sxc[chan + 1] = a.y * inv;
        sxc[chan + 2] = a.z * inv; sxc[chan + 3] = a.w * inv;
        float4 mm = *reinterpret_cast<float4*>(&smax[0][chan]);
        sxc[64 + chan + 0] = mm.x; sxc[64 + chan + 1] = mm.y;
        sxc[64 + chan + 2] = mm.z; sxc[64 + chan + 3] = mm.w;
    }
    __syncthreads();

    int wid = tid >> 5;
    if (wid < 2) {
        int lane = tid & 31;
        int head = wid;
        const float* W1p = head ? Wo1 : Wa1;
        const float* b1p = head ? bo1 : ba1;
        const float* W2p = head ? Wo2 : Wa2;
        const float* b2p = head ? bo2 : ba2;
        float a0 = b1p[lane], a1 = b1p[lane + 32];
#pragma unroll 4
        for (int k = 0; k < 128; k++) {
            float v = sxc[k];
            a0 += v * W1p[k * 64 + lane];
            a1 += v * W1p[k * 64 + lane + 32];
        }
        a0 = fmaxf(a0, 0.f); a1 = fmaxf(a1, 0.f);
        float o = a0 * W2p[lane] + a1 * W2p[lane + 32];
#pragma unroll
        for (int off = 16; off; off >>= 1) o += __shfl_xor_sync(0xffffffffu, o, off);
        if (lane == 0) outp[head * GG + g] = o + b2p[0];
    }
}

// ---------------- launch (2-stream overlap, capture-safe fork/join) ----------------
extern "C" void kernel_launch(void* const* d_in, const int* in_sizes, int n_in,
                              void* d_out, int out_size)
{
    const float*    metadata = (const float*)d_in[0];
    const float*    wf       = (const float*)d_in[1];
    const unsigned* eiw      = (const unsigned*)d_in[2];
    const unsigned* batchw   = (const unsigned*)d_in[3];
    const float* Wm  = (const float*)d_in[4];
    const float* bm  = (const float*)d_in[5];
    const float* Ww  = (const float*)d_in[6];
    const float* bw  = (const float*)d_in[7];
    const float* Wc  = (const float*)d_in[8];
    const float* bc  = (const float*)d_in[9];
    const float* W1  = (const float*)d_in[10];
    const float* b1  = (const float*)d_in[11];
    const float* W2  = (const float*)d_in[12];
    const float* b2  = (const float*)d_in[13];
    const float* g1  = (const float*)d_in[14];
    const float* be1 = (const float*)d_in[15];
    const float* g2  = (const float*)d_in[16];
    const float* be2 = (const float*)d_in[17];
    const float* Wla1 = (const float*)d_in[18];
    const float* bla1 = (const float*)d_in[19];
    const float* Wla2 = (const float*)d_in[20];
    const float* bla2 = (const float*)d_in[21];
    const float* Wlo1 = (const float*)d_in[22];
    const float* blo1 = (const float*)d_in[23];
    const float* Wlo2 = (const float*)d_in[24];
    const float* blo2 = (const float*)d_in[25];
    float* outp = (float*)d_out;

    const int NB = (NN + 255) / 256;
    const int EB = (EE + 255) / 256;
    const int GB = (NN + 127) / 128;          // 391
    const int AB = (NN * 16 + 255) / 256;     // 3125

    static cudaStream_t s1 = nullptr;
    static cudaEvent_t ev0 = nullptr, ev_scan = nullptr, ev_g1 = nullptr;
    if (s1 == nullptr) {
        cudaStreamCreateWithFlags(&s1, cudaStreamNonBlocking);
        cudaEventCreateWithFlags(&ev0, cudaEventDisableTiming);
        cudaEventCreateWithFlags(&ev_scan, cudaEventDisableTiming);
        cudaEventCreateWithFlags(&ev_g1, cudaEventDisableTiming);
    }

    cudaEventRecord(ev0, 0);
    cudaStreamWaitEvent(s1, ev0, 0);

    // stream 0: graph build
    k_setup<<<NB, 256>>>(eiw);
    k_degree<<<EB, 256>>>(eiw);
    k_scanrsqrt<<<1, 1024>>>();
    cudaEventRecord(ev_scan, 0);
    k_fill<<<EB, 256>>>(eiw);

    // stream 1: encoder (independent), then GEMM1 after deg ready
    k_enc<<<GB, 256, 0, s1>>>(metadata, wf, Wm, bm, Ww, bw, Wc, bc);
    cudaStreamWaitEvent(s1, ev_scan, 0);
    k_gcn_gemm<1, 1><<<GB, 256, 0, s1>>>(W1, nullptr, nullptr);
    cudaEventRecord(ev_g1, s1);

    // join
    cudaStreamWaitEvent(0, ev_g1, 0);
    k_gatherbn<4, 0, 1><<<AB, 256>>>(b1, nullptr, nullptr);

    k_gcn_gemm<3, 4><<<GB, 256>>>(W2, g1, be1);
    k_gatherbn<5, 1, 2><<<AB, 256>>>(b2, g1, be1);

    k_poolheads<<<GG, 256>>>(batchw, g2, be2,
                             Wla1, bla1, Wla2, bla2, Wlo1, blo1, Wlo2, blo2, outp);
}